// round 11
// baseline (speedup 1.0000x reference)
#include <cuda_runtime.h>
#include <cuda_fp16.h>
#include <cstdint>
#include <cstddef>

// Problem constants
#define BATCH 2
#define SEQ   2048
#define EMB   1024
#define HEADS 16
#define DHEAD 64
#define ROWS  (BATCH*SEQ)          // 4096
#define FFDIM (4*EMB)              // 4096

// ---------------- scratch (allocation-free: __device__ globals) ----------------
__device__ unsigned short g_h   [ROWS*EMB];
__device__ unsigned short g_q   [ROWS*EMB];
__device__ unsigned short g_k   [ROWS*EMB];
__device__ unsigned short g_v   [ROWS*EMB];
__device__ unsigned short g_vt  [32*DHEAD*SEQ];   // V transposed: [bh][d][s]
__device__ unsigned short g_attn[ROWS*EMB];
__device__ unsigned short g_ffn [ROWS*FFDIM];
__device__ float          g_x1  [ROWS*EMB];
// transposed weights, [N, K] K-major, fp16
__device__ unsigned short g_wqt [EMB*EMB];
__device__ unsigned short g_wkt [EMB*EMB];
__device__ unsigned short g_wvt [EMB*EMB];
__device__ unsigned short g_wpt [EMB*EMB];
__device__ unsigned short g_w1t [EMB*FFDIM];
__device__ unsigned short g_w2t [FFDIM*EMB];

// ======================= PTX helpers =========================================
__device__ __forceinline__ uint32_t smem_u32(const void* p) {
    uint32_t a;
    asm("{ .reg .u64 t; cvta.to.shared.u64 t, %1; cvt.u32.u64 %0, t; }"
        : "=r"(a) : "l"(p));
    return a;
}
#define CP_ASYNC16(dst, src) \
    asm volatile("cp.async.cg.shared.global [%0], [%1], 16;" \
                 :: "r"(dst), "l"(src) : "memory")
#define CP_COMMIT() asm volatile("cp.async.commit_group;" ::: "memory")
#define CP_WAIT1()  asm volatile("cp.async.wait_group 1;"  ::: "memory")
__device__ __forceinline__ void ldmx4(uint32_t* r, uint32_t addr) {
    asm volatile("ldmatrix.sync.aligned.m8n8.x4.shared.b16 {%0,%1,%2,%3}, [%4];"
                 : "=r"(r[0]), "=r"(r[1]), "=r"(r[2]), "=r"(r[3]) : "r"(addr));
}
__device__ __forceinline__ uint32_t packh2(float lo, float hi) {
    __half2 h = __floats2half2_rn(lo, hi);
    return *reinterpret_cast<uint32_t*>(&h);
}
__device__ __forceinline__ void mmaf16(float* c,
                                       uint32_t a0, uint32_t a1,
                                       uint32_t a2, uint32_t a3,
                                       uint32_t b0, uint32_t b1) {
    asm volatile(
        "mma.sync.aligned.m16n8k16.row.col.f32.f16.f16.f32 "
        "{%0,%1,%2,%3}, {%4,%5,%6,%7}, {%8,%9}, {%0,%1,%2,%3};"
        : "+f"(c[0]), "+f"(c[1]), "+f"(c[2]), "+f"(c[3])
        : "r"(a0), "r"(a1), "r"(a2), "r"(a3), "r"(b0), "r"(b1));
}

// ======================= tensor-core fp16 GEMM (cp.async + ldmatrix) =========
// C[M,N] = A[M,K]*Bt[N,K]^T, fp16 in / fp32 accum.
// CTA 128x256, warp tile 64x64 (8 warps = 2m x 4n). BK=64 halves (128B/row),
// XOR-8 swizzle col^(row&7). 3-stage cp.async ring, 48KB/stage.
#define G_ASTG  16384
#define G_STAGE 49152
#define G_SMEM  (3 * G_STAGE)      // 147456

__global__ void __launch_bounds__(256)
gemm_mma(const __half* __restrict__ A, const __half* __restrict__ Bt,
         void* __restrict__ Cv,
         const float* __restrict__ bias,
         const float* __restrict__ residual,
         int doRelu, int K, int N, int halfOut) {
    extern __shared__ __align__(128) char smem[];
    uint32_t sbase = smem_u32(smem);
    int t = threadIdx.x;
    int lane = t & 31, wid = t >> 5;
    int g = lane >> 2, tg = lane & 3;
    int warp_m = wid & 1, warp_n = wid >> 1;
    int m0 = blockIdx.y * 128, n0 = blockIdx.x * 256;

    // cp.async: A rows 128 -> thread t>>1, 4 units; B rows 256 -> thread t, 8 units
    int arow_ld = t >> 1, ac0 = (t & 1) * 4;
    const __half* Ag = A  + (size_t)(m0 + arow_ld) * K;
    const __half* Bg = Bt + (size_t)(n0 + t) * K;
    uint32_t a_ldoff = (uint32_t)arow_ld * 128;
    int a_ldswz = arow_ld & 7;
    uint32_t b_ldoff = (uint32_t)t * 128;
    int b_ldswz = t & 7;

    // ldmatrix geometry
    int sub = lane >> 3, r_in = lane & 7;
    uint32_t a_row[4], a_swz[4];
#pragma unroll
    for (int mf = 0; mf < 4; mf++) {
        int r = warp_m * 64 + mf * 16 + (sub & 1) * 8 + r_in;
        a_row[mf] = (uint32_t)r * 128;
        a_swz[mf] = (uint32_t)(r & 7);
    }
    int a_du = sub >> 1;
    uint32_t b_row[8], b_swz[8];
#pragma unroll
    for (int nf = 0; nf < 8; nf++) {
        int r = warp_n * 64 + nf * 8 + r_in;
        b_row[nf] = (uint32_t)r * 128;
        b_swz[nf] = (uint32_t)(r & 7);
    }

    float acc[4][8][4];
#pragma unroll
    for (int i = 0; i < 4; i++)
#pragma unroll
        for (int j = 0; j < 8; j++)
#pragma unroll
            for (int r = 0; r < 4; r++) acc[i][j][r] = 0.f;

#define G_ISSUE(s, k0)                                                        \
    do {                                                                      \
        uint32_t ab_ = sbase + (s) * G_STAGE;                                 \
        uint32_t bb_ = ab_ + G_ASTG;                                          \
        _Pragma("unroll")                                                     \
        for (int j = 0; j < 4; j++) {                                         \
            int c_ = ac0 + j;                                                 \
            CP_ASYNC16(ab_ + a_ldoff + (uint32_t)(c_ ^ a_ldswz) * 16,         \
                       Ag + (k0) + c_ * 8);                                   \
        }                                                                     \
        _Pragma("unroll")                                                     \
        for (int j = 0; j < 8; j++) {                                         \
            CP_ASYNC16(bb_ + b_ldoff + (uint32_t)(j ^ b_ldswz) * 16,          \
                       Bg + (k0) + j * 8);                                    \
        }                                                                     \
    } while (0)

    int NKt = K >> 6;
    G_ISSUE(0, 0);  CP_COMMIT();
    G_ISSUE(1, 64); CP_COMMIT();

    int s = 0;
    for (int it = 0; it < NKt; it++) {
        CP_WAIT1();
        __syncthreads();
        int snext = (s == 2) ? 0 : s + 1;
        int sfill = (snext == 2) ? 0 : snext + 1;
        if (it + 2 < NKt) G_ISSUE(sfill, (it + 2) << 6);
        CP_COMMIT();

        uint32_t abase = sbase + s * G_STAGE;
        uint32_t bbase = abase + G_ASTG;
#pragma unroll
        for (int kp = 0; kp < 2; kp++) {
            uint32_t bfr[8][4];
#pragma unroll
            for (int nf = 0; nf < 8; nf++) {
                uint32_t u = (uint32_t)(kp * 4 + sub) ^ b_swz[nf];
                ldmx4(bfr[nf], bbase + b_row[nf] + u * 16);
            }
#pragma unroll
            for (int kss = 0; kss < 2; kss++) {
                int ks = kp * 2 + kss;
                uint32_t afr[4][4];
#pragma unroll
                for (int mf = 0; mf < 4; mf++) {
                    uint32_t u = (uint32_t)(2 * ks + a_du) ^ a_swz[mf];
                    ldmx4(afr[mf], abase + a_row[mf] + u * 16);
                }
#pragma unroll
                for (int mf = 0; mf < 4; mf++)
#pragma unroll
                    for (int nf = 0; nf < 8; nf++)
                        mmaf16(acc[mf][nf],
                               afr[mf][0], afr[mf][1], afr[mf][2], afr[mf][3],
                               bfr[nf][kss * 2], bfr[nf][kss * 2 + 1]);
            }
        }
        s = snext;
    }

    // epilogue
#pragma unroll
    for (int mf = 0; mf < 4; mf++) {
#pragma unroll
        for (int nf = 0; nf < 8; nf++) {
            int row = m0 + warp_m * 64 + mf * 16 + g;
            int col = n0 + warp_n * 64 + nf * 8 + 2 * tg;
            float b0 = 0.f, b1 = 0.f;
            if (bias) { b0 = bias[col]; b1 = bias[col + 1]; }
#pragma unroll
            for (int rr = 0; rr < 2; rr++) {
                int r = row + rr * 8;
                float v0 = acc[mf][nf][rr * 2 + 0] + b0;
                float v1 = acc[mf][nf][rr * 2 + 1] + b1;
                if (doRelu) { v0 = fmaxf(v0, 0.f); v1 = fmaxf(v1, 0.f); }
                if (residual) {
                    float2 rv = *(const float2*)(residual + (size_t)r * N + col);
                    v0 += rv.x; v1 += rv.y;
                }
                if (halfOut) {
                    *(uint32_t*)((__half*)Cv + (size_t)r * N + col) = packh2(v0, v1);
                } else {
                    *(float2*)((float*)Cv + (size_t)r * N + col) = make_float2(v0, v1);
                }
            }
        }
    }
}

// ======================= weight transpose (fp32 in -> fp16 out) ==============
__global__ void transpose_w(const float* __restrict__ in, __half* __restrict__ out,
                            int K, int N, int headMode) {
    __shared__ float tile[32][33];
    int k0 = blockIdx.y * 32, n0 = blockIdx.x * 32;
    int tx = threadIdx.x, ty = threadIdx.y;
    for (int i = ty; i < 32; i += 8) {
        int k = k0 + i, n = n0 + tx;
        float v = headMode
            ? in[(size_t)(n >> 6) * K * 64 + (size_t)k * 64 + (n & 63)]
            : in[(size_t)k * N + n];
        tile[i][tx] = v;
    }
    __syncthreads();
    for (int i = ty; i < 32; i += 8) {
        out[(size_t)(n0 + i) * K + k0 + tx] = __float2half(tile[tx][i]);
    }
}

// ======================= V transpose (fp16): [b,s,h*64+d] -> [bh][d][s] ======
__global__ void transpose_v(const unsigned short* __restrict__ v,
                            unsigned short* __restrict__ vt) {
    __shared__ unsigned short tile[32][33];
    int bh = blockIdx.z;
    int s0 = blockIdx.x * 32, d0 = blockIdx.y * 32;
    int b = bh >> 4, h = bh & 15;
    int tx = threadIdx.x, ty = threadIdx.y;
    for (int i = ty; i < 32; i += 8)
        tile[i][tx] = v[(size_t)(b * SEQ + s0 + i) * EMB + h * 64 + d0 + tx];
    __syncthreads();
    for (int i = ty; i < 32; i += 8)
        vt[((size_t)bh * 64 + d0 + i) * SEQ + s0 + tx] = tile[tx][i];
}

// ======================= LayerNorm (fp32 in -> fp16 out) =====================
__global__ void ln_kernel(const float* __restrict__ x,
                          const float* __restrict__ g,
                          const float* __restrict__ b,
                          __half* __restrict__ out) {
    int row = blockIdx.x;
    const float* xr = x + (size_t)row * EMB;
    float v[4];
    float s = 0.f, ss = 0.f;
#pragma unroll
    for (int i = 0; i < 4; i++) {
        v[i] = xr[threadIdx.x + i * 256];
        s += v[i]; ss += v[i] * v[i];
    }
#pragma unroll
    for (int m = 16; m; m >>= 1) {
        s  += __shfl_xor_sync(0xffffffffu, s,  m);
        ss += __shfl_xor_sync(0xffffffffu, ss, m);
    }
    __shared__ float red[2][8];
    int warp = threadIdx.x >> 5, lane = threadIdx.x & 31;
    if (lane == 0) { red[0][warp] = s; red[1][warp] = ss; }
    __syncthreads();
    float S = 0.f, SS = 0.f;
#pragma unroll
    for (int w = 0; w < 8; w++) { S += red[0][w]; SS += red[1][w]; }
    float mean = S * (1.f / EMB);
    float var  = SS * (1.f / EMB) - mean * mean;
    float inv  = rsqrtf(var + 1e-5f);
    __half* orow = out + (size_t)row * EMB;
#pragma unroll
    for (int i = 0; i < 4; i++) {
        int e = threadIdx.x + i * 256;
        orow[e] = __float2half((v[i] - mean) * inv * g[e] + b[e]);
    }
}

// ======================= Flash attention, cp.async + ldmatrix ================
// Br=128 (8 warps x 16 rows), Bc=64, d=64; P in registers.
// Q: permuted-slab layout (unchanged). K/V: XOR-8 swizzle rows(64)x128B,
// 3-stage cp.async ring, ldmatrix fragments (same mapping as GEMM B operand).
#define FQSLAB 520
#define FQSUB  2080
#define FQ_BYTES 16640                   // 4160 u32
#define FKV_STG 8192
#define FL_KOFF FQ_BYTES                 // 16640 (128-aligned)
#define FL_VOFF (FQ_BYTES + 3 * FKV_STG)
#define FL_SMEM (FQ_BYTES + 6 * FKV_STG) // 65792

__global__ void __launch_bounds__(256)
flash_mma(const __half* __restrict__ Q, const __half* __restrict__ Kg,
          const __half* __restrict__ Vt, __half* __restrict__ O) {
    extern __shared__ __align__(128) char fsm[];
    uint32_t sbase = smem_u32(fsm);
    uint32_t* Qs = (uint32_t*)fsm;
    int t = threadIdx.x, lane = t & 31, w = t >> 5;
    int g = lane >> 2, tg = lane & 3;
    int sub = lane >> 3, r_in = lane & 7;
    int bh = blockIdx.y;
    int row0 = blockIdx.x * 128;
    size_t baseQ = (size_t)(bh >> 4) * SEQ * EMB + (size_t)(bh & 15) * DHEAD;
    size_t baseV = (size_t)bh * DHEAD * SEQ;
    const __half2 qscale = __float2half2_rn(0.125f);

    // cp.async K/V: 512 units each, thread t -> rows (2t)>>3, cols (2t+j)&7
    int kv_i0 = t * 2;

#define F_ISSUE(st, kt0)                                                      \
    do {                                                                      \
        uint32_t kb_ = sbase + FL_KOFF + (st) * FKV_STG;                      \
        uint32_t vb_ = sbase + FL_VOFF + (st) * FKV_STG;                      \
        _Pragma("unroll")                                                     \
        for (int j = 0; j < 2; j++) {                                         \
            int idx = kv_i0 + j;                                              \
            int r_ = idx >> 3, c_ = idx & 7;                                  \
            uint32_t dst = (uint32_t)r_ * 128 + (uint32_t)(c_ ^ (r_ & 7)) * 16; \
            CP_ASYNC16(kb_ + dst, Kg + baseQ + (size_t)((kt0) + r_) * EMB + c_ * 8); \
            CP_ASYNC16(vb_ + dst, Vt + baseV + (size_t)r_ * SEQ + (kt0) + c_ * 8);  \
        }                                                                     \
    } while (0)

    // load Q tile (scale by 2^-3)
    for (int i = t; i < 1024; i += 256) {
        int r = i >> 3, q = i & 7;
        uint4 p = *(const uint4*)(Q + baseQ + (size_t)(row0 + r) * EMB + q * 8);
        uint32_t un[4] = {p.x, p.y, p.z, p.w};
#pragma unroll
        for (int jj = 0; jj < 4; jj++) {
            __half2 hv = *reinterpret_cast<__half2*>(&un[jj]);
            hv = __hmul2(hv, qscale);
            int u = q * 4 + jj;
            int s_ = u >> 4, uu = u & 15;
            Qs[s_ * FQSUB + (uu & 3) * FQSLAB + r * 4 + (uu >> 2)]
                = *reinterpret_cast<uint32_t*>(&hv);
        }
    }
    F_ISSUE(0, 0);  CP_COMMIT();
    F_ISSUE(1, 64); CP_COMMIT();
    __syncthreads();

    int rA = w * 16 + g, rB = rA + 8;
    uint4 qfA[2], qfB[2];
#pragma unroll
    for (int s2 = 0; s2 < 2; s2++) {
        qfA[s2] = *(const uint4*)&Qs[s2 * FQSUB + tg * FQSLAB + rA * 4];
        qfB[s2] = *(const uint4*)&Qs[s2 * FQSUB + tg * FQSLAB + rB * 4];
    }

    float m0 = -1e30f, m1 = -1e30f, l0 = 0.f, l1 = 0.f;
    float oacc[8][4];
#pragma unroll
    for (int i = 0; i < 8; i++)
#pragma unroll
        for (int j = 0; j < 4; j++) oacc[i][j] = 0.f;

    uint32_t lrow = (uint32_t)r_in * 128;   // r_in component of ldmatrix rows

    int st = 0;
    for (int it = 0; it < 32; it++) {
        CP_WAIT1();
        __syncthreads();
        int snext = (st == 2) ? 0 : st + 1;
        int sfill = (snext == 2) ? 0 : snext + 1;
        if (it + 2 < 32) F_ISSUE(sfill, (it + 2) * 64);
        CP_COMMIT();

        uint32_t kbase = sbase + FL_KOFF + st * FKV_STG;
        uint32_t vbase = sbase + FL_VOFF + st * FKV_STG;

        // S = Q K^T
        float sacc[8][4];
#pragma unroll
        for (int i = 0; i < 8; i++)
#pragma unroll
            for (int j = 0; j < 4; j++) sacc[i][j] = 0.f;
#pragma unroll
        for (int kp = 0; kp < 2; kp++) {
            uint4 qa = qfA[kp], qb = qfB[kp];
#pragma unroll
            for (int nb = 0; nb < 8; nb++) {
                int rr = nb * 8 + r_in;
                uint32_t u = (uint32_t)(kp * 4 + sub) ^ (uint32_t)(rr & 7);
                uint32_t kfr[4];
                ldmx4(kfr, kbase + (uint32_t)nb * 1024 + lrow + u * 16);
                mmaf16(sacc[nb], qa.x, qb.x, qa.y, qb.y, kfr[0], kfr[1]);
                mmaf16(sacc[nb], qa.z, qb.z, qa.w, qb.w, kfr[2], kfr[3]);
            }
        }

        // online softmax
        float mxA = -1e30f, mxB = -1e30f;
#pragma unroll
        for (int nb = 0; nb < 8; nb++) {
            mxA = fmaxf(mxA, fmaxf(sacc[nb][0], sacc[nb][1]));
            mxB = fmaxf(mxB, fmaxf(sacc[nb][2], sacc[nb][3]));
        }
        mxA = fmaxf(mxA, __shfl_xor_sync(0xffffffffu, mxA, 1));
        mxA = fmaxf(mxA, __shfl_xor_sync(0xffffffffu, mxA, 2));
        mxB = fmaxf(mxB, __shfl_xor_sync(0xffffffffu, mxB, 1));
        mxB = fmaxf(mxB, __shfl_xor_sync(0xffffffffu, mxB, 2));
        float mnA = fmaxf(m0, mxA), mnB = fmaxf(m1, mxB);
        float cA = __expf(m0 - mnA), cB = __expf(m1 - mnB);
        m0 = mnA; m1 = mnB;
        float rsA = 0.f, rsB = 0.f;
#pragma unroll
        for (int nb = 0; nb < 8; nb++) {
            sacc[nb][0] = __expf(sacc[nb][0] - mnA);
            sacc[nb][1] = __expf(sacc[nb][1] - mnA);
            sacc[nb][2] = __expf(sacc[nb][2] - mnB);
            sacc[nb][3] = __expf(sacc[nb][3] - mnB);
            rsA += sacc[nb][0] + sacc[nb][1];
            rsB += sacc[nb][2] + sacc[nb][3];
        }
        rsA += __shfl_xor_sync(0xffffffffu, rsA, 1);
        rsA += __shfl_xor_sync(0xffffffffu, rsA, 2);
        rsB += __shfl_xor_sync(0xffffffffu, rsB, 1);
        rsB += __shfl_xor_sync(0xffffffffu, rsB, 2);
        l0 = l0 * cA + rsA;
        l1 = l1 * cB + rsB;
#pragma unroll
        for (int db = 0; db < 8; db++) {
            oacc[db][0] *= cA; oacc[db][1] *= cA;
            oacc[db][2] *= cB; oacc[db][3] *= cB;
        }

        // pack P fragments
        uint32_t a0[4], a1[4], a2[4], a3[4];
#pragma unroll
        for (int s2 = 0; s2 < 4; s2++) {
            a0[s2] = packh2(sacc[2 * s2][0],     sacc[2 * s2][1]);
            a1[s2] = packh2(sacc[2 * s2][2],     sacc[2 * s2][3]);
            a2[s2] = packh2(sacc[2 * s2 + 1][0], sacc[2 * s2 + 1][1]);
            a3[s2] = packh2(sacc[2 * s2 + 1][2], sacc[2 * s2 + 1][3]);
        }

        // O += P V
#pragma unroll
        for (int db = 0; db < 8; db++) {
            int rr = db * 8 + r_in;
#pragma unroll
            for (int kp = 0; kp < 2; kp++) {
                uint32_t u = (uint32_t)(kp * 4 + sub) ^ (uint32_t)(rr & 7);
                uint32_t vfr[4];
                ldmx4(vfr, vbase + (uint32_t)db * 1024 + lrow + u * 16);
                int s0 = 2 * kp, s1 = s0 + 1;
                mmaf16(oacc[db], a0[s0], a1[s0], a2[s0], a3[s0], vfr[0], vfr[1]);
                mmaf16(oacc[db], a0[s1], a1[s1], a2[s1], a3[s1], vfr[2], vfr[3]);
            }
        }
        st = snext;
    }

    float iA = 1.f / l0, iB = 1.f / l1;
#pragma unroll
    for (int db = 0; db < 8; db++) {
        int c = db * 8 + 2 * tg;
        *(uint32_t*)(O + baseQ + (size_t)(row0 + rA) * EMB + c) =
            packh2(oacc[db][0] * iA, oacc[db][1] * iA);
        *(uint32_t*)(O + baseQ + (size_t)(row0 + rB) * EMB + c) =
            packh2(oacc[db][2] * iB, oacc[db][3] * iB);
    }
}

// ======================= host orchestration =================================
extern "C" void kernel_launch(void* const* d_in, const int* in_sizes, int n_in,
                              void* d_out, int out_size) {
    const float* x     = (const float*)d_in[0];
    const float* Wq    = (const float*)d_in[1];
    const float* Wk    = (const float*)d_in[2];
    const float* Wv    = (const float*)d_in[3];
    const float* Wproj = (const float*)d_in[4];
    const float* bproj = (const float*)d_in[5];
    const float* W1    = (const float*)d_in[6];
    const float* b1    = (const float*)d_in[7];
    const float* W2    = (const float*)d_in[8];
    const float* b2    = (const float*)d_in[9];
    const float* g1    = (const float*)d_in[10];
    const float* be1   = (const float*)d_in[11];
    const float* g2    = (const float*)d_in[12];
    const float* be2   = (const float*)d_in[13];
    float* out = (float*)d_out;

    void *ph, *pq, *pk, *pv, *pvt, *pattn, *px1, *pffn;
    void *pwq, *pwk, *pwv, *pwp, *pw1, *pw2;
    cudaGetSymbolAddress(&ph,    g_h);
    cudaGetSymbolAddress(&pq,    g_q);
    cudaGetSymbolAddress(&pk,    g_k);
    cudaGetSymbolAddress(&pv,    g_v);
    cudaGetSymbolAddress(&pvt,   g_vt);
    cudaGetSymbolAddress(&pattn, g_attn);
    cudaGetSymbolAddress(&px1,   g_x1);
    cudaGetSymbolAddress(&pffn,  g_ffn);
    cudaGetSymbolAddress(&pwq,   g_wqt);
    cudaGetSymbolAddress(&pwk,   g_wkt);
    cudaGetSymbolAddress(&pwv,   g_wvt);
    cudaGetSymbolAddress(&pwp,   g_wpt);
    cudaGetSymbolAddress(&pw1,   g_w1t);
    cudaGetSymbolAddress(&pw2,   g_w2t);
    __half* f_h    = (__half*)ph;
    __half* f_q    = (__half*)pq;
    __half* f_k    = (__half*)pk;
    __half* f_v    = (__half*)pv;
    __half* f_vt   = (__half*)pvt;
    __half* f_attn = (__half*)pattn;
    float*  f_x1   = (float*)px1;
    __half* f_ffn  = (__half*)pffn;

    cudaFuncSetAttribute(gemm_mma, cudaFuncAttributeMaxDynamicSharedMemorySize,
                         G_SMEM);
    cudaFuncSetAttribute(flash_mma, cudaFuncAttributeMaxDynamicSharedMemorySize,
                         FL_SMEM);

    dim3 tb(32, 8);
    dim3 gP(EMB / 256, ROWS / 128);     // (4, 32)
    dim3 gF1(FFDIM / 256, ROWS / 128);  // (16, 32)

    ln_kernel<<<ROWS, 256>>>(x, g1, be1, f_h);
    transpose_w<<<dim3(EMB / 32, EMB / 32), tb>>>(Wq, (__half*)pwq, EMB, EMB, 1);
    transpose_w<<<dim3(EMB / 32, EMB / 32), tb>>>(Wk, (__half*)pwk, EMB, EMB, 1);
    transpose_w<<<dim3(EMB / 32, EMB / 32), tb>>>(Wv, (__half*)pwv, EMB, EMB, 1);
    transpose_w<<<dim3(EMB / 32, EMB / 32), tb>>>(Wproj, (__half*)pwp, EMB, EMB, 0);

    gemm_mma<<<gP, 256, G_SMEM>>>(f_h, (__half*)pwq, f_q, nullptr, nullptr, 0, EMB, EMB, 1);
    gemm_mma<<<gP, 256, G_SMEM>>>(f_h, (__half*)pwk, f_k, nullptr, nullptr, 0, EMB, EMB, 1);
    gemm_mma<<<gP, 256, G_SMEM>>>(f_h, (__half*)pwv, f_v, nullptr, nullptr, 0, EMB, EMB, 1);

    transpose_v<<<dim3(SEQ / 32, DHEAD / 32, 32), tb>>>(
        (const unsigned short*)pv, (unsigned short*)pvt);
    flash_mma<<<dim3(SEQ / 128, 32), 256, FL_SMEM>>>(f_q, f_k, f_vt, f_attn);

    gemm_mma<<<gP, 256, G_SMEM>>>(f_attn, (__half*)pwp, f_x1, bproj, x, 0, EMB, EMB, 0);
    ln_kernel<<<ROWS, 256>>>(f_x1, g2, be2, f_h);

    transpose_w<<<dim3(FFDIM / 32, EMB / 32), tb>>>(W1, (__half*)pw1, EMB, FFDIM, 0);
    transpose_w<<<dim3(EMB / 32, FFDIM / 32), tb>>>(W2, (__half*)pw2, FFDIM, EMB, 0);

    gemm_mma<<<gF1, 256, G_SMEM>>>(f_h, (__half*)pw1, f_ffn, b1, nullptr, 1, EMB, FFDIM, 1);
    gemm_mma<<<gP, 256, G_SMEM>>>(f_ffn, (__half*)pw2, out, b2, f_x1, 0, FFDIM, EMB, 0);
}

// round 12
// speedup vs baseline: 1.1376x; 1.1376x over previous
#include <cuda_runtime.h>
#include <cuda_fp16.h>
#include <cstdint>
#include <cstddef>

// Problem constants
#define BATCH 2
#define SEQ   2048
#define EMB   1024
#define HEADS 16
#define DHEAD 64
#define ROWS  (BATCH*SEQ)          // 4096
#define FFDIM (4*EMB)              // 4096

// ---------------- scratch (allocation-free: __device__ globals) ----------------
__device__ unsigned short g_h   [ROWS*EMB];
__device__ unsigned short g_q   [ROWS*EMB];
__device__ unsigned short g_k   [ROWS*EMB];
__device__ unsigned short g_v   [ROWS*EMB];
__device__ unsigned short g_vt  [32*DHEAD*SEQ];   // V transposed: [bh][d][s]
__device__ unsigned short g_attn[ROWS*EMB];
__device__ unsigned short g_ffn [ROWS*FFDIM];
__device__ float          g_x1  [ROWS*EMB];
// transposed weights, [N, K] K-major, fp16
__device__ unsigned short g_wqt [EMB*EMB];
__device__ unsigned short g_wkt [EMB*EMB];
__device__ unsigned short g_wvt [EMB*EMB];
__device__ unsigned short g_wpt [EMB*EMB];
__device__ unsigned short g_w1t [EMB*FFDIM];
__device__ unsigned short g_w2t [FFDIM*EMB];

// ======================= PTX helpers =========================================
__device__ __forceinline__ uint32_t smem_u32(const void* p) {
    uint32_t a;
    asm("{ .reg .u64 t; cvta.to.shared.u64 t, %1; cvt.u32.u64 %0, t; }"
        : "=r"(a) : "l"(p));
    return a;
}
#define CP_ASYNC16(dst, src) \
    asm volatile("cp.async.cg.shared.global [%0], [%1], 16;" \
                 :: "r"(dst), "l"(src) : "memory")
#define CP_COMMIT() asm volatile("cp.async.commit_group;" ::: "memory")
#define CP_WAIT1()  asm volatile("cp.async.wait_group 1;"  ::: "memory")
__device__ __forceinline__ void ldmx4(uint32_t* r, uint32_t addr) {
    asm volatile("ldmatrix.sync.aligned.m8n8.x4.shared.b16 {%0,%1,%2,%3}, [%4];"
                 : "=r"(r[0]), "=r"(r[1]), "=r"(r[2]), "=r"(r[3]) : "r"(addr));
}
__device__ __forceinline__ uint32_t packh2(float lo, float hi) {
    __half2 h = __floats2half2_rn(lo, hi);
    return *reinterpret_cast<uint32_t*>(&h);
}
__device__ __forceinline__ void mmaf16(float* c,
                                       uint32_t a0, uint32_t a1,
                                       uint32_t a2, uint32_t a3,
                                       uint32_t b0, uint32_t b1) {
    asm volatile(
        "mma.sync.aligned.m16n8k16.row.col.f32.f16.f16.f32 "
        "{%0,%1,%2,%3}, {%4,%5,%6,%7}, {%8,%9}, {%0,%1,%2,%3};"
        : "+f"(c[0]), "+f"(c[1]), "+f"(c[2]), "+f"(c[3])
        : "r"(a0), "r"(a1), "r"(a2), "r"(a3), "r"(b0), "r"(b1));
}

// ======================= tensor-core fp16 GEMM (R8 measured version) =========
// C[M,N] = A[M,K]*Bt[N,K]^T, fp16 in / fp32 accum.
// BM=BN=128, BK=64 halves (128B/row, 8 x 16B units), XOR-8 swizzle col^(row&7).
// 3-stage cp.async ring (32KB/stage -> 2 CTAs/SM); 256 thr, warp tile 64x32.
#define G_STAGE 32768              // A 16KB + B 16KB
#define G_SMEM  (3 * G_STAGE)      // 98304

__global__ void __launch_bounds__(256)
gemm_mma(const __half* __restrict__ A, const __half* __restrict__ Bt,
         void* __restrict__ Cv,
         const float* __restrict__ bias,
         const float* __restrict__ residual,
         int doRelu, int K, int N, int halfOut) {
    extern __shared__ __align__(128) char smem[];
    uint32_t sbase = smem_u32(smem);
    int t = threadIdx.x;
    int lane = t & 31, wid = t >> 5;
    int g = lane >> 2, tg = lane & 3;
    int warp_m = wid & 1, warp_n = wid >> 1;
    int m0 = blockIdx.y * 128, n0 = blockIdx.x * 128;

    // cp.async assignment: thread t -> row t>>1, units (t&1)*4 .. +3
    int ld_row = t >> 1, ld_c0 = (t & 1) * 4;
    const __half* Arow = A  + (size_t)(m0 + ld_row) * K;
    const __half* Brow = Bt + (size_t)(n0 + ld_row) * K;
    int ld_swz = ld_row & 7;
    uint32_t ld_off = (uint32_t)ld_row * 128;

    // ldmatrix per-lane geometry
    int sub = lane >> 3, r_in = lane & 7;
    uint32_t a_row[4], a_swz[4];
#pragma unroll
    for (int mf = 0; mf < 4; mf++) {
        int r = warp_m * 64 + mf * 16 + (sub & 1) * 8 + r_in;
        a_row[mf] = (uint32_t)r * 128;
        a_swz[mf] = (uint32_t)(r & 7);
    }
    int a_du = sub >> 1;
    uint32_t b_row[4], b_swz[4];
#pragma unroll
    for (int nf = 0; nf < 4; nf++) {
        int r = warp_n * 32 + nf * 8 + r_in;
        b_row[nf] = (uint32_t)r * 128;
        b_swz[nf] = (uint32_t)(r & 7);
    }

    float acc[4][4][4];
#pragma unroll
    for (int i = 0; i < 4; i++)
#pragma unroll
        for (int j = 0; j < 4; j++)
#pragma unroll
            for (int r = 0; r < 4; r++) acc[i][j][r] = 0.f;

#define G_ISSUE(s, k0)                                                        \
    do {                                                                      \
        uint32_t ab_ = sbase + (s) * G_STAGE + ld_off;                        \
        uint32_t bb_ = ab_ + 16384;                                           \
        _Pragma("unroll")                                                     \
        for (int j = 0; j < 4; j++) {                                         \
            int c_ = ld_c0 + j;                                               \
            uint32_t cp_ = (uint32_t)(c_ ^ ld_swz) * 16;                      \
            CP_ASYNC16(ab_ + cp_, Arow + (k0) + c_ * 8);                      \
            CP_ASYNC16(bb_ + cp_, Brow + (k0) + c_ * 8);                      \
        }                                                                     \
    } while (0)

    int NKt = K >> 6;   // K = 1024 or 4096 -> 16 / 64 tiles
    G_ISSUE(0, 0);  CP_COMMIT();
    G_ISSUE(1, 64); CP_COMMIT();

    int s = 0;
    for (int it = 0; it < NKt; it++) {
        CP_WAIT1();
        __syncthreads();
        int snext = (s == 2) ? 0 : s + 1;
        int sfill = (snext == 2) ? 0 : snext + 1;
        if (it + 2 < NKt) G_ISSUE(sfill, (it + 2) << 6);
        CP_COMMIT();

        uint32_t abase = sbase + s * G_STAGE;
        uint32_t bbase = abase + 16384;
#pragma unroll
        for (int kp = 0; kp < 2; kp++) {
            uint32_t bfr[4][4];
#pragma unroll
            for (int nf = 0; nf < 4; nf++) {
                uint32_t u = (uint32_t)(kp * 4 + sub) ^ b_swz[nf];
                ldmx4(bfr[nf], bbase + b_row[nf] + u * 16);
            }
#pragma unroll
            for (int kss = 0; kss < 2; kss++) {
                int ks = kp * 2 + kss;
                uint32_t afr[4][4];
#pragma unroll
                for (int mf = 0; mf < 4; mf++) {
                    uint32_t u = (uint32_t)(2 * ks + a_du) ^ a_swz[mf];
                    ldmx4(afr[mf], abase + a_row[mf] + u * 16);
                }
#pragma unroll
                for (int mf = 0; mf < 4; mf++)
#pragma unroll
                    for (int nf = 0; nf < 4; nf++)
                        mmaf16(acc[mf][nf],
                               afr[mf][0], afr[mf][1], afr[mf][2], afr[mf][3],
                               bfr[nf][kss * 2], bfr[nf][kss * 2 + 1]);
            }
        }
        s = snext;
    }

    // epilogue
#pragma unroll
    for (int mf = 0; mf < 4; mf++) {
#pragma unroll
        for (int nf = 0; nf < 4; nf++) {
            int row = m0 + warp_m * 64 + mf * 16 + g;
            int col = n0 + warp_n * 32 + nf * 8 + 2 * tg;
            float b0 = 0.f, b1 = 0.f;
            if (bias) { b0 = bias[col]; b1 = bias[col + 1]; }
#pragma unroll
            for (int rr = 0; rr < 2; rr++) {
                int r = row + rr * 8;
                float v0 = acc[mf][nf][rr * 2 + 0] + b0;
                float v1 = acc[mf][nf][rr * 2 + 1] + b1;
                if (doRelu) { v0 = fmaxf(v0, 0.f); v1 = fmaxf(v1, 0.f); }
                if (residual) {
                    float2 rv = *(const float2*)(residual + (size_t)r * N + col);
                    v0 += rv.x; v1 += rv.y;
                }
                if (halfOut) {
                    *(uint32_t*)((__half*)Cv + (size_t)r * N + col) = packh2(v0, v1);
                } else {
                    *(float2*)((float*)Cv + (size_t)r * N + col) = make_float2(v0, v1);
                }
            }
        }
    }
}

// ======================= weight transpose (fp32 in -> fp16 out) ==============
__global__ void transpose_w(const float* __restrict__ in, __half* __restrict__ out,
                            int K, int N, int headMode) {
    __shared__ float tile[32][33];
    int k0 = blockIdx.y * 32, n0 = blockIdx.x * 32;
    int tx = threadIdx.x, ty = threadIdx.y;
    for (int i = ty; i < 32; i += 8) {
        int k = k0 + i, n = n0 + tx;
        float v = headMode
            ? in[(size_t)(n >> 6) * K * 64 + (size_t)k * 64 + (n & 63)]
            : in[(size_t)k * N + n];
        tile[i][tx] = v;
    }
    __syncthreads();
    for (int i = ty; i < 32; i += 8) {
        out[(size_t)(n0 + i) * K + k0 + tx] = __float2half(tile[tx][i]);
    }
}

// ======================= V transpose (fp16): [b,s,h*64+d] -> [bh][d][s] ======
__global__ void transpose_v(const unsigned short* __restrict__ v,
                            unsigned short* __restrict__ vt) {
    __shared__ unsigned short tile[32][33];
    int bh = blockIdx.z;
    int s0 = blockIdx.x * 32, d0 = blockIdx.y * 32;
    int b = bh >> 4, h = bh & 15;
    int tx = threadIdx.x, ty = threadIdx.y;
    for (int i = ty; i < 32; i += 8)
        tile[i][tx] = v[(size_t)(b * SEQ + s0 + i) * EMB + h * 64 + d0 + tx];
    __syncthreads();
    for (int i = ty; i < 32; i += 8)
        vt[((size_t)bh * 64 + d0 + i) * SEQ + s0 + tx] = tile[tx][i];
}

// ======================= LayerNorm (fp32 in -> fp16 out) =====================
__global__ void ln_kernel(const float* __restrict__ x,
                          const float* __restrict__ g,
                          const float* __restrict__ b,
                          __half* __restrict__ out) {
    int row = blockIdx.x;
    const float* xr = x + (size_t)row * EMB;
    float v[4];
    float s = 0.f, ss = 0.f;
#pragma unroll
    for (int i = 0; i < 4; i++) {
        v[i] = xr[threadIdx.x + i * 256];
        s += v[i]; ss += v[i] * v[i];
    }
#pragma unroll
    for (int m = 16; m; m >>= 1) {
        s  += __shfl_xor_sync(0xffffffffu, s,  m);
        ss += __shfl_xor_sync(0xffffffffu, ss, m);
    }
    __shared__ float red[2][8];
    int warp = threadIdx.x >> 5, lane = threadIdx.x & 31;
    if (lane == 0) { red[0][warp] = s; red[1][warp] = ss; }
    __syncthreads();
    float S = 0.f, SS = 0.f;
#pragma unroll
    for (int w = 0; w < 8; w++) { S += red[0][w]; SS += red[1][w]; }
    float mean = S * (1.f / EMB);
    float var  = SS * (1.f / EMB) - mean * mean;
    float inv  = rsqrtf(var + 1e-5f);
    __half* orow = out + (size_t)row * EMB;
#pragma unroll
    for (int i = 0; i < 4; i++) {
        int e = threadIdx.x + i * 256;
        orow[e] = __float2half((v[i] - mean) * inv * g[e] + b[e]);
    }
}

// ======================= Flash attention, cp.async + ldmatrix ================
// Br=128 (8 warps x 16 rows), Bc=64, d=64; P in registers.
// Q: permuted-slab layout. K/V: XOR-8 swizzle rows(64)x128B,
// 3-stage cp.async ring, ldmatrix fragments.
#define FQSLAB 520
#define FQSUB  2080
#define FQ_BYTES 16640                   // 4160 u32
#define FKV_STG 8192
#define FL_KOFF FQ_BYTES                 // 16640 (128-aligned)
#define FL_VOFF (FQ_BYTES + 3 * FKV_STG)
#define FL_SMEM (FQ_BYTES + 6 * FKV_STG) // 65792

__global__ void __launch_bounds__(256)
flash_mma(const __half* __restrict__ Q, const __half* __restrict__ Kg,
          const __half* __restrict__ Vt, __half* __restrict__ O) {
    extern __shared__ __align__(128) char fsm[];
    uint32_t sbase = smem_u32(fsm);
    uint32_t* Qs = (uint32_t*)fsm;
    int t = threadIdx.x, lane = t & 31, w = t >> 5;
    int g = lane >> 2, tg = lane & 3;
    int sub = lane >> 3, r_in = lane & 7;
    int bh = blockIdx.y;
    int row0 = blockIdx.x * 128;
    size_t baseQ = (size_t)(bh >> 4) * SEQ * EMB + (size_t)(bh & 15) * DHEAD;
    size_t baseV = (size_t)bh * DHEAD * SEQ;
    const __half2 qscale = __float2half2_rn(0.125f);

    // cp.async K/V: 512 units each, thread t -> 2 units
    int kv_i0 = t * 2;

#define F_ISSUE(st, kt0)                                                      \
    do {                                                                      \
        uint32_t kb_ = sbase + FL_KOFF + (st) * FKV_STG;                      \
        uint32_t vb_ = sbase + FL_VOFF + (st) * FKV_STG;                      \
        _Pragma("unroll")                                                     \
        for (int j = 0; j < 2; j++) {                                         \
            int idx = kv_i0 + j;                                              \
            int r_ = idx >> 3, c_ = idx & 7;                                  \
            uint32_t dst = (uint32_t)r_ * 128 + (uint32_t)(c_ ^ (r_ & 7)) * 16; \
            CP_ASYNC16(kb_ + dst, Kg + baseQ + (size_t)((kt0) + r_) * EMB + c_ * 8); \
            CP_ASYNC16(vb_ + dst, Vt + baseV + (size_t)r_ * SEQ + (kt0) + c_ * 8);  \
        }                                                                     \
    } while (0)

    // load Q tile (scale by 2^-3)
    for (int i = t; i < 1024; i += 256) {
        int r = i >> 3, q = i & 7;
        uint4 p = *(const uint4*)(Q + baseQ + (size_t)(row0 + r) * EMB + q * 8);
        uint32_t un[4] = {p.x, p.y, p.z, p.w};
#pragma unroll
        for (int jj = 0; jj < 4; jj++) {
            __half2 hv = *reinterpret_cast<__half2*>(&un[jj]);
            hv = __hmul2(hv, qscale);
            int u = q * 4 + jj;
            int s_ = u >> 4, uu = u & 15;
            Qs[s_ * FQSUB + (uu & 3) * FQSLAB + r * 4 + (uu >> 2)]
                = *reinterpret_cast<uint32_t*>(&hv);
        }
    }
    F_ISSUE(0, 0);  CP_COMMIT();
    F_ISSUE(1, 64); CP_COMMIT();
    __syncthreads();

    int rA = w * 16 + g, rB = rA + 8;
    uint4 qfA[2], qfB[2];
#pragma unroll
    for (int s2 = 0; s2 < 2; s2++) {
        qfA[s2] = *(const uint4*)&Qs[s2 * FQSUB + tg * FQSLAB + rA * 4];
        qfB[s2] = *(const uint4*)&Qs[s2 * FQSUB + tg * FQSLAB + rB * 4];
    }

    float m0 = -1e30f, m1 = -1e30f, l0 = 0.f, l1 = 0.f;
    float oacc[8][4];
#pragma unroll
    for (int i = 0; i < 8; i++)
#pragma unroll
        for (int j = 0; j < 4; j++) oacc[i][j] = 0.f;

    uint32_t lrow = (uint32_t)r_in * 128;

    int st = 0;
    for (int it = 0; it < 32; it++) {
        CP_WAIT1();
        __syncthreads();
        int snext = (st == 2) ? 0 : st + 1;
        int sfill = (snext == 2) ? 0 : snext + 1;
        if (it + 2 < 32) F_ISSUE(sfill, (it + 2) * 64);
        CP_COMMIT();

        uint32_t kbase = sbase + FL_KOFF + st * FKV_STG;
        uint32_t vbase = sbase + FL_VOFF + st * FKV_STG;

        // S = Q K^T
        float sacc[8][4];
#pragma unroll
        for (int i = 0; i < 8; i++)
#pragma unroll
            for (int j = 0; j < 4; j++) sacc[i][j] = 0.f;
#pragma unroll
        for (int kp = 0; kp < 2; kp++) {
            uint4 qa = qfA[kp], qb = qfB[kp];
#pragma unroll
            for (int nb = 0; nb < 8; nb++) {
                int rr = nb * 8 + r_in;
                uint32_t u = (uint32_t)(kp * 4 + sub) ^ (uint32_t)(rr & 7);
                uint32_t kfr[4];
                ldmx4(kfr, kbase + (uint32_t)nb * 1024 + lrow + u * 16);
                mmaf16(sacc[nb], qa.x, qb.x, qa.y, qb.y, kfr[0], kfr[1]);
                mmaf16(sacc[nb], qa.z, qb.z, qa.w, qb.w, kfr[2], kfr[3]);
            }
        }

        // online softmax
        float mxA = -1e30f, mxB = -1e30f;
#pragma unroll
        for (int nb = 0; nb < 8; nb++) {
            mxA = fmaxf(mxA, fmaxf(sacc[nb][0], sacc[nb][1]));
            mxB = fmaxf(mxB, fmaxf(sacc[nb][2], sacc[nb][3]));
        }
        mxA = fmaxf(mxA, __shfl_xor_sync(0xffffffffu, mxA, 1));
        mxA = fmaxf(mxA, __shfl_xor_sync(0xffffffffu, mxA, 2));
        mxB = fmaxf(mxB, __shfl_xor_sync(0xffffffffu, mxB, 1));
        mxB = fmaxf(mxB, __shfl_xor_sync(0xffffffffu, mxB, 2));
        float mnA = fmaxf(m0, mxA), mnB = fmaxf(m1, mxB);
        float cA = __expf(m0 - mnA), cB = __expf(m1 - mnB);
        m0 = mnA; m1 = mnB;
        float rsA = 0.f, rsB = 0.f;
#pragma unroll
        for (int nb = 0; nb < 8; nb++) {
            sacc[nb][0] = __expf(sacc[nb][0] - mnA);
            sacc[nb][1] = __expf(sacc[nb][1] - mnA);
            sacc[nb][2] = __expf(sacc[nb][2] - mnB);
            sacc[nb][3] = __expf(sacc[nb][3] - mnB);
            rsA += sacc[nb][0] + sacc[nb][1];
            rsB += sacc[nb][2] + sacc[nb][3];
        }
        rsA += __shfl_xor_sync(0xffffffffu, rsA, 1);
        rsA += __shfl_xor_sync(0xffffffffu, rsA, 2);
        rsB += __shfl_xor_sync(0xffffffffu, rsB, 1);
        rsB += __shfl_xor_sync(0xffffffffu, rsB, 2);
        l0 = l0 * cA + rsA;
        l1 = l1 * cB + rsB;
#pragma unroll
        for (int db = 0; db < 8; db++) {
            oacc[db][0] *= cA; oacc[db][1] *= cA;
            oacc[db][2] *= cB; oacc[db][3] *= cB;
        }

        // pack P fragments
        uint32_t a0[4], a1[4], a2[4], a3[4];
#pragma unroll
        for (int s2 = 0; s2 < 4; s2++) {
            a0[s2] = packh2(sacc[2 * s2][0],     sacc[2 * s2][1]);
            a1[s2] = packh2(sacc[2 * s2][2],     sacc[2 * s2][3]);
            a2[s2] = packh2(sacc[2 * s2 + 1][0], sacc[2 * s2 + 1][1]);
            a3[s2] = packh2(sacc[2 * s2 + 1][2], sacc[2 * s2 + 1][3]);
        }

        // O += P V
#pragma unroll
        for (int db = 0; db < 8; db++) {
            int rr = db * 8 + r_in;
#pragma unroll
            for (int kp = 0; kp < 2; kp++) {
                uint32_t u = (uint32_t)(kp * 4 + sub) ^ (uint32_t)(rr & 7);
                uint32_t vfr[4];
                ldmx4(vfr, vbase + (uint32_t)db * 1024 + lrow + u * 16);
                int s0 = 2 * kp, s1 = s0 + 1;
                mmaf16(oacc[db], a0[s0], a1[s0], a2[s0], a3[s0], vfr[0], vfr[1]);
                mmaf16(oacc[db], a0[s1], a1[s1], a2[s1], a3[s1], vfr[2], vfr[3]);
            }
        }
        st = snext;
    }

    float iA = 1.f / l0, iB = 1.f / l1;
#pragma unroll
    for (int db = 0; db < 8; db++) {
        int c = db * 8 + 2 * tg;
        *(uint32_t*)(O + baseQ + (size_t)(row0 + rA) * EMB + c) =
            packh2(oacc[db][0] * iA, oacc[db][1] * iA);
        *(uint32_t*)(O + baseQ + (size_t)(row0 + rB) * EMB + c) =
            packh2(oacc[db][2] * iB, oacc[db][3] * iB);
    }
}

// ======================= host orchestration =================================
extern "C" void kernel_launch(void* const* d_in, const int* in_sizes, int n_in,
                              void* d_out, int out_size) {
    const float* x     = (const float*)d_in[0];
    const float* Wq    = (const float*)d_in[1];
    const float* Wk    = (const float*)d_in[2];
    const float* Wv    = (const float*)d_in[3];
    const float* Wproj = (const float*)d_in[4];
    const float* bproj = (const float*)d_in[5];
    const float* W1    = (const float*)d_in[6];
    const float* b1    = (const float*)d_in[7];
    const float* W2    = (const float*)d_in[8];
    const float* b2    = (const float*)d_in[9];
    const float* g1    = (const float*)d_in[10];
    const float* be1   = (const float*)d_in[11];
    const float* g2    = (const float*)d_in[12];
    const float* be2   = (const float*)d_in[13];
    float* out = (float*)d_out;

    void *ph, *pq, *pk, *pv, *pvt, *pattn, *px1, *pffn;
    void *pwq, *pwk, *pwv, *pwp, *pw1, *pw2;
    cudaGetSymbolAddress(&ph,    g_h);
    cudaGetSymbolAddress(&pq,    g_q);
    cudaGetSymbolAddress(&pk,    g_k);
    cudaGetSymbolAddress(&pv,    g_v);
    cudaGetSymbolAddress(&pvt,   g_vt);
    cudaGetSymbolAddress(&pattn, g_attn);
    cudaGetSymbolAddress(&px1,   g_x1);
    cudaGetSymbolAddress(&pffn,  g_ffn);
    cudaGetSymbolAddress(&pwq,   g_wqt);
    cudaGetSymbolAddress(&pwk,   g_wkt);
    cudaGetSymbolAddress(&pwv,   g_wvt);
    cudaGetSymbolAddress(&pwp,   g_wpt);
    cudaGetSymbolAddress(&pw1,   g_w1t);
    cudaGetSymbolAddress(&pw2,   g_w2t);
    __half* f_h    = (__half*)ph;
    __half* f_q    = (__half*)pq;
    __half* f_k    = (__half*)pk;
    __half* f_v    = (__half*)pv;
    __half* f_vt   = (__half*)pvt;
    __half* f_attn = (__half*)pattn;
    float*  f_x1   = (float*)px1;
    __half* f_ffn  = (__half*)pffn;

    cudaFuncSetAttribute(gemm_mma, cudaFuncAttributeMaxDynamicSharedMemorySize,
                         G_SMEM);
    cudaFuncSetAttribute(flash_mma, cudaFuncAttributeMaxDynamicSharedMemorySize,
                         FL_SMEM);

    dim3 tb(32, 8);
    dim3 gP(EMB / 128, ROWS / 128);     // (8, 32)
    dim3 gF1(FFDIM / 128, ROWS / 128);  // (32, 32)

    ln_kernel<<<ROWS, 256>>>(x, g1, be1, f_h);
    transpose_w<<<dim3(EMB / 32, EMB / 32), tb>>>(Wq, (__half*)pwq, EMB, EMB, 1);
    transpose_w<<<dim3(EMB / 32, EMB / 32), tb>>>(Wk, (__half*)pwk, EMB, EMB, 1);
    transpose_w<<<dim3(EMB / 32, EMB / 32), tb>>>(Wv, (__half*)pwv, EMB, EMB, 1);
    transpose_w<<<dim3(EMB / 32, EMB / 32), tb>>>(Wproj, (__half*)pwp, EMB, EMB, 0);

    gemm_mma<<<gP, 256, G_SMEM>>>(f_h, (__half*)pwq, f_q, nullptr, nullptr, 0, EMB, EMB, 1);
    gemm_mma<<<gP, 256, G_SMEM>>>(f_h, (__half*)pwk, f_k, nullptr, nullptr, 0, EMB, EMB, 1);
    gemm_mma<<<gP, 256, G_SMEM>>>(f_h, (__half*)pwv, f_v, nullptr, nullptr, 0, EMB, EMB, 1);

    transpose_v<<<dim3(SEQ / 32, DHEAD / 32, 32), tb>>>(
        (const unsigned short*)pv, (unsigned short*)pvt);
    flash_mma<<<dim3(SEQ / 128, 32), 256, FL_SMEM>>>(f_q, f_k, f_vt, f_attn);

    gemm_mma<<<gP, 256, G_SMEM>>>(f_attn, (__half*)pwp, f_x1, bproj, x, 0, EMB, EMB, 0);
    ln_kernel<<<ROWS, 256>>>(f_x1, g2, be2, f_h);

    transpose_w<<<dim3(FFDIM / 32, EMB / 32), tb>>>(W1, (__half*)pw1, EMB, FFDIM, 0);
    transpose_w<<<dim3(EMB / 32, FFDIM / 32), tb>>>(W2, (__half*)pw2, FFDIM, EMB, 0);

    gemm_mma<<<gF1, 256, G_SMEM>>>(f_h, (__half*)pw1, f_ffn, b1, nullptr, 1, EMB, FFDIM, 1);
    gemm_mma<<<gP, 256, G_SMEM>>>(f_ffn, (__half*)pw2, out, b2, f_x1, 0, FFDIM, EMB, 0);
}

// round 13
// speedup vs baseline: 1.1380x; 1.0003x over previous
#include <cuda_runtime.h>
#include <cuda_fp16.h>
#include <cstdint>
#include <cstddef>

// Problem constants
#define BATCH 2
#define SEQ   2048
#define EMB   1024
#define HEADS 16
#define DHEAD 64
#define ROWS  (BATCH*SEQ)          // 4096
#define FFDIM (4*EMB)              // 4096

// ---------------- scratch (allocation-free: __device__ globals) ----------------
__device__ unsigned short g_h   [ROWS*EMB];
__device__ unsigned short g_q   [ROWS*EMB];
__device__ unsigned short g_k   [ROWS*EMB];
__device__ unsigned short g_v   [ROWS*EMB];
__device__ unsigned short g_vt  [32*DHEAD*SEQ];   // V transposed: [bh][d][s]
__device__ unsigned short g_attn[ROWS*EMB];
__device__ unsigned short g_ffn [ROWS*FFDIM];
__device__ float          g_x1  [ROWS*EMB];
// transposed weights, [N, K] K-major, fp16
__device__ unsigned short g_wqt [EMB*EMB];
__device__ unsigned short g_wkt [EMB*EMB];
__device__ unsigned short g_wvt [EMB*EMB];
__device__ unsigned short g_wpt [EMB*EMB];
__device__ unsigned short g_w1t [EMB*FFDIM];
__device__ unsigned short g_w2t [FFDIM*EMB];

// ======================= PTX helpers =========================================
__device__ __forceinline__ uint32_t smem_u32(const void* p) {
    uint32_t a;
    asm("{ .reg .u64 t; cvta.to.shared.u64 t, %1; cvt.u32.u64 %0, t; }"
        : "=r"(a) : "l"(p));
    return a;
}
#define CP_ASYNC16(dst, src) \
    asm volatile("cp.async.cg.shared.global [%0], [%1], 16;" \
                 :: "r"(dst), "l"(src) : "memory")
#define CP_COMMIT() asm volatile("cp.async.commit_group;" ::: "memory")
#define CP_WAIT1()  asm volatile("cp.async.wait_group 1;"  ::: "memory")
__device__ __forceinline__ void ldmx4(uint32_t* r, uint32_t addr) {
    asm volatile("ldmatrix.sync.aligned.m8n8.x4.shared.b16 {%0,%1,%2,%3}, [%4];"
                 : "=r"(r[0]), "=r"(r[1]), "=r"(r[2]), "=r"(r[3]) : "r"(addr));
}
__device__ __forceinline__ uint32_t packh2(float lo, float hi) {
    __half2 h = __floats2half2_rn(lo, hi);
    return *reinterpret_cast<uint32_t*>(&h);
}
__device__ __forceinline__ void mmaf16(float* c,
                                       uint32_t a0, uint32_t a1,
                                       uint32_t a2, uint32_t a3,
                                       uint32_t b0, uint32_t b1) {
    asm volatile(
        "mma.sync.aligned.m16n8k16.row.col.f32.f16.f16.f32 "
        "{%0,%1,%2,%3}, {%4,%5,%6,%7}, {%8,%9}, {%0,%1,%2,%3};"
        : "+f"(c[0]), "+f"(c[1]), "+f"(c[2]), "+f"(c[3])
        : "r"(a0), "r"(a1), "r"(a2), "r"(a3), "r"(b0), "r"(b1));
}

// ======================= tensor-core fp16 GEMM (R8 measured version) =========
// C[M,N] = A[M,K]*Bt[N,K]^T, fp16 in / fp32 accum.
// BM=BN=128, BK=64 halves (128B/row, 8 x 16B units), XOR-8 swizzle col^(row&7).
// 3-stage cp.async ring (32KB/stage -> 2 CTAs/SM); 256 thr, warp tile 64x32.
#define G_STAGE 32768              // A 16KB + B 16KB
#define G_SMEM  (3 * G_STAGE)      // 98304

__global__ void __launch_bounds__(256)
gemm_mma(const __half* __restrict__ A, const __half* __restrict__ Bt,
         void* __restrict__ Cv,
         const float* __restrict__ bias,
         const float* __restrict__ residual,
         int doRelu, int K, int N, int halfOut) {
    extern __shared__ __align__(128) char smem[];
    uint32_t sbase = smem_u32(smem);
    int t = threadIdx.x;
    int lane = t & 31, wid = t >> 5;
    int g = lane >> 2, tg = lane & 3;
    int warp_m = wid & 1, warp_n = wid >> 1;
    int m0 = blockIdx.y * 128, n0 = blockIdx.x * 128;

    // cp.async assignment: thread t -> row t>>1, units (t&1)*4 .. +3
    int ld_row = t >> 1, ld_c0 = (t & 1) * 4;
    const __half* Arow = A  + (size_t)(m0 + ld_row) * K;
    const __half* Brow = Bt + (size_t)(n0 + ld_row) * K;
    int ld_swz = ld_row & 7;
    uint32_t ld_off = (uint32_t)ld_row * 128;

    // ldmatrix per-lane geometry
    int sub = lane >> 3, r_in = lane & 7;
    uint32_t a_row[4], a_swz[4];
#pragma unroll
    for (int mf = 0; mf < 4; mf++) {
        int r = warp_m * 64 + mf * 16 + (sub & 1) * 8 + r_in;
        a_row[mf] = (uint32_t)r * 128;
        a_swz[mf] = (uint32_t)(r & 7);
    }
    int a_du = sub >> 1;
    uint32_t b_row[4], b_swz[4];
#pragma unroll
    for (int nf = 0; nf < 4; nf++) {
        int r = warp_n * 32 + nf * 8 + r_in;
        b_row[nf] = (uint32_t)r * 128;
        b_swz[nf] = (uint32_t)(r & 7);
    }

    float acc[4][4][4];
#pragma unroll
    for (int i = 0; i < 4; i++)
#pragma unroll
        for (int j = 0; j < 4; j++)
#pragma unroll
            for (int r = 0; r < 4; r++) acc[i][j][r] = 0.f;

#define G_ISSUE(s, k0)                                                        \
    do {                                                                      \
        uint32_t ab_ = sbase + (s) * G_STAGE + ld_off;                        \
        uint32_t bb_ = ab_ + 16384;                                           \
        _Pragma("unroll")                                                     \
        for (int j = 0; j < 4; j++) {                                         \
            int c_ = ld_c0 + j;                                               \
            uint32_t cp_ = (uint32_t)(c_ ^ ld_swz) * 16;                      \
            CP_ASYNC16(ab_ + cp_, Arow + (k0) + c_ * 8);                      \
            CP_ASYNC16(bb_ + cp_, Brow + (k0) + c_ * 8);                      \
        }                                                                     \
    } while (0)

    int NKt = K >> 6;   // K = 1024 or 4096 -> 16 / 64 tiles
    G_ISSUE(0, 0);  CP_COMMIT();
    G_ISSUE(1, 64); CP_COMMIT();

    int s = 0;
    for (int it = 0; it < NKt; it++) {
        CP_WAIT1();
        __syncthreads();
        int snext = (s == 2) ? 0 : s + 1;
        int sfill = (snext == 2) ? 0 : snext + 1;
        if (it + 2 < NKt) G_ISSUE(sfill, (it + 2) << 6);
        CP_COMMIT();

        uint32_t abase = sbase + s * G_STAGE;
        uint32_t bbase = abase + 16384;
#pragma unroll
        for (int kp = 0; kp < 2; kp++) {
            uint32_t bfr[4][4];
#pragma unroll
            for (int nf = 0; nf < 4; nf++) {
                uint32_t u = (uint32_t)(kp * 4 + sub) ^ b_swz[nf];
                ldmx4(bfr[nf], bbase + b_row[nf] + u * 16);
            }
#pragma unroll
            for (int kss = 0; kss < 2; kss++) {
                int ks = kp * 2 + kss;
                uint32_t afr[4][4];
#pragma unroll
                for (int mf = 0; mf < 4; mf++) {
                    uint32_t u = (uint32_t)(2 * ks + a_du) ^ a_swz[mf];
                    ldmx4(afr[mf], abase + a_row[mf] + u * 16);
                }
#pragma unroll
                for (int mf = 0; mf < 4; mf++)
#pragma unroll
                    for (int nf = 0; nf < 4; nf++)
                        mmaf16(acc[mf][nf],
                               afr[mf][0], afr[mf][1], afr[mf][2], afr[mf][3],
                               bfr[nf][kss * 2], bfr[nf][kss * 2 + 1]);
            }
        }
        s = snext;
    }

    // epilogue
#pragma unroll
    for (int mf = 0; mf < 4; mf++) {
#pragma unroll
        for (int nf = 0; nf < 4; nf++) {
            int row = m0 + warp_m * 64 + mf * 16 + g;
            int col = n0 + warp_n * 32 + nf * 8 + 2 * tg;
            float b0 = 0.f, b1 = 0.f;
            if (bias) { b0 = bias[col]; b1 = bias[col + 1]; }
#pragma unroll
            for (int rr = 0; rr < 2; rr++) {
                int r = row + rr * 8;
                float v0 = acc[mf][nf][rr * 2 + 0] + b0;
                float v1 = acc[mf][nf][rr * 2 + 1] + b1;
                if (doRelu) { v0 = fmaxf(v0, 0.f); v1 = fmaxf(v1, 0.f); }
                if (residual) {
                    float2 rv = *(const float2*)(residual + (size_t)r * N + col);
                    v0 += rv.x; v1 += rv.y;
                }
                if (halfOut) {
                    *(uint32_t*)((__half*)Cv + (size_t)r * N + col) = packh2(v0, v1);
                } else {
                    *(float2*)((float*)Cv + (size_t)r * N + col) = make_float2(v0, v1);
                }
            }
        }
    }
}

// ======================= weight transpose (fp32 in -> fp16 out) ==============
__global__ void transpose_w(const float* __restrict__ in, __half* __restrict__ out,
                            int K, int N, int headMode) {
    __shared__ float tile[32][33];
    int k0 = blockIdx.y * 32, n0 = blockIdx.x * 32;
    int tx = threadIdx.x, ty = threadIdx.y;
    for (int i = ty; i < 32; i += 8) {
        int k = k0 + i, n = n0 + tx;
        float v = headMode
            ? in[(size_t)(n >> 6) * K * 64 + (size_t)k * 64 + (n & 63)]
            : in[(size_t)k * N + n];
        tile[i][tx] = v;
    }
    __syncthreads();
    for (int i = ty; i < 32; i += 8) {
        out[(size_t)(n0 + i) * K + k0 + tx] = __float2half(tile[tx][i]);
    }
}

// ======================= V transpose (fp16): [b,s,h*64+d] -> [bh][d][s] ======
__global__ void transpose_v(const unsigned short* __restrict__ v,
                            unsigned short* __restrict__ vt) {
    __shared__ unsigned short tile[32][33];
    int bh = blockIdx.z;
    int s0 = blockIdx.x * 32, d0 = blockIdx.y * 32;
    int b = bh >> 4, h = bh & 15;
    int tx = threadIdx.x, ty = threadIdx.y;
    for (int i = ty; i < 32; i += 8)
        tile[i][tx] = v[(size_t)(b * SEQ + s0 + i) * EMB + h * 64 + d0 + tx];
    __syncthreads();
    for (int i = ty; i < 32; i += 8)
        vt[((size_t)bh * 64 + d0 + i) * SEQ + s0 + tx] = tile[tx][i];
}

// ======================= LayerNorm (fp32 in -> fp16 out) =====================
__global__ void ln_kernel(const float* __restrict__ x,
                          const float* __restrict__ g,
                          const float* __restrict__ b,
                          __half* __restrict__ out) {
    int row = blockIdx.x;
    const float* xr = x + (size_t)row * EMB;
    float v[4];
    float s = 0.f, ss = 0.f;
#pragma unroll
    for (int i = 0; i < 4; i++) {
        v[i] = xr[threadIdx.x + i * 256];
        s += v[i]; ss += v[i] * v[i];
    }
#pragma unroll
    for (int m = 16; m; m >>= 1) {
        s  += __shfl_xor_sync(0xffffffffu, s,  m);
        ss += __shfl_xor_sync(0xffffffffu, ss, m);
    }
    __shared__ float red[2][8];
    int warp = threadIdx.x >> 5, lane = threadIdx.x & 31;
    if (lane == 0) { red[0][warp] = s; red[1][warp] = ss; }
    __syncthreads();
    float S = 0.f, SS = 0.f;
#pragma unroll
    for (int w = 0; w < 8; w++) { S += red[0][w]; SS += red[1][w]; }
    float mean = S * (1.f / EMB);
    float var  = SS * (1.f / EMB) - mean * mean;
    float inv  = rsqrtf(var + 1e-5f);
    __half* orow = out + (size_t)row * EMB;
#pragma unroll
    for (int i = 0; i < 4; i++) {
        int e = threadIdx.x + i * 256;
        orow[e] = __float2half((v[i] - mean) * inv * g[e] + b[e]);
    }
}

// ======================= Flash attention, cp.async + ldmatrix ================
// Br=128 (8 warps x 16 rows), Bc=64, d=64; P in registers.
// Q: permuted-slab layout. K/V: XOR-8 swizzle rows(64)x128B,
// 3-stage cp.async ring, ldmatrix fragments.
#define FQSLAB 520
#define FQSUB  2080
#define FQ_BYTES 16640                   // 4160 u32
#define FKV_STG 8192
#define FL_KOFF FQ_BYTES                 // 16640 (128-aligned)
#define FL_VOFF (FQ_BYTES + 3 * FKV_STG)
#define FL_SMEM (FQ_BYTES + 6 * FKV_STG) // 65792

__global__ void __launch_bounds__(256)
flash_mma(const __half* __restrict__ Q, const __half* __restrict__ Kg,
          const __half* __restrict__ Vt, __half* __restrict__ O) {
    extern __shared__ __align__(128) char fsm[];
    uint32_t sbase = smem_u32(fsm);
    uint32_t* Qs = (uint32_t*)fsm;
    int t = threadIdx.x, lane = t & 31, w = t >> 5;
    int g = lane >> 2, tg = lane & 3;
    int sub = lane >> 3, r_in = lane & 7;
    int bh = blockIdx.y;
    int row0 = blockIdx.x * 128;
    size_t baseQ = (size_t)(bh >> 4) * SEQ * EMB + (size_t)(bh & 15) * DHEAD;
    size_t baseV = (size_t)bh * DHEAD * SEQ;
    const __half2 qscale = __float2half2_rn(0.125f);

    // cp.async K/V: 512 units each, thread t -> 2 units
    int kv_i0 = t * 2;

#define F_ISSUE(st, kt0)                                                      \
    do {                                                                      \
        uint32_t kb_ = sbase + FL_KOFF + (st) * FKV_STG;                      \
        uint32_t vb_ = sbase + FL_VOFF + (st) * FKV_STG;                      \
        _Pragma("unroll")                                                     \
        for (int j = 0; j < 2; j++) {                                         \
            int idx = kv_i0 + j;                                              \
            int r_ = idx >> 3, c_ = idx & 7;                                  \
            uint32_t dst = (uint32_t)r_ * 128 + (uint32_t)(c_ ^ (r_ & 7)) * 16; \
            CP_ASYNC16(kb_ + dst, Kg + baseQ + (size_t)((kt0) + r_) * EMB + c_ * 8); \
            CP_ASYNC16(vb_ + dst, Vt + baseV + (size_t)r_ * SEQ + (kt0) + c_ * 8);  \
        }                                                                     \
    } while (0)

    // load Q tile (scale by 2^-3)
    for (int i = t; i < 1024; i += 256) {
        int r = i >> 3, q = i & 7;
        uint4 p = *(const uint4*)(Q + baseQ + (size_t)(row0 + r) * EMB + q * 8);
        uint32_t un[4] = {p.x, p.y, p.z, p.w};
#pragma unroll
        for (int jj = 0; jj < 4; jj++) {
            __half2 hv = *reinterpret_cast<__half2*>(&un[jj]);
            hv = __hmul2(hv, qscale);
            int u = q * 4 + jj;
            int s_ = u >> 4, uu = u & 15;
            Qs[s_ * FQSUB + (uu & 3) * FQSLAB + r * 4 + (uu >> 2)]
                = *reinterpret_cast<uint32_t*>(&hv);
        }
    }
    F_ISSUE(0, 0);  CP_COMMIT();
    F_ISSUE(1, 64); CP_COMMIT();
    __syncthreads();

    int rA = w * 16 + g, rB = rA + 8;
    uint4 qfA[2], qfB[2];
#pragma unroll
    for (int s2 = 0; s2 < 2; s2++) {
        qfA[s2] = *(const uint4*)&Qs[s2 * FQSUB + tg * FQSLAB + rA * 4];
        qfB[s2] = *(const uint4*)&Qs[s2 * FQSUB + tg * FQSLAB + rB * 4];
    }

    float m0 = -1e30f, m1 = -1e30f, l0 = 0.f, l1 = 0.f;
    float oacc[8][4];
#pragma unroll
    for (int i = 0; i < 8; i++)
#pragma unroll
        for (int j = 0; j < 4; j++) oacc[i][j] = 0.f;

    uint32_t lrow = (uint32_t)r_in * 128;

    int st = 0;
    for (int it = 0; it < 32; it++) {
        CP_WAIT1();
        __syncthreads();
        int snext = (st == 2) ? 0 : st + 1;
        int sfill = (snext == 2) ? 0 : snext + 1;
        if (it + 2 < 32) F_ISSUE(sfill, (it + 2) * 64);
        CP_COMMIT();

        uint32_t kbase = sbase + FL_KOFF + st * FKV_STG;
        uint32_t vbase = sbase + FL_VOFF + st * FKV_STG;

        // S = Q K^T
        float sacc[8][4];
#pragma unroll
        for (int i = 0; i < 8; i++)
#pragma unroll
            for (int j = 0; j < 4; j++) sacc[i][j] = 0.f;
#pragma unroll
        for (int kp = 0; kp < 2; kp++) {
            uint4 qa = qfA[kp], qb = qfB[kp];
#pragma unroll
            for (int nb = 0; nb < 8; nb++) {
                int rr = nb * 8 + r_in;
                uint32_t u = (uint32_t)(kp * 4 + sub) ^ (uint32_t)(rr & 7);
                uint32_t kfr[4];
                ldmx4(kfr, kbase + (uint32_t)nb * 1024 + lrow + u * 16);
                mmaf16(sacc[nb], qa.x, qb.x, qa.y, qb.y, kfr[0], kfr[1]);
                mmaf16(sacc[nb], qa.z, qb.z, qa.w, qb.w, kfr[2], kfr[3]);
            }
        }

        // online softmax
        float mxA = -1e30f, mxB = -1e30f;
#pragma unroll
        for (int nb = 0; nb < 8; nb++) {
            mxA = fmaxf(mxA, fmaxf(sacc[nb][0], sacc[nb][1]));
            mxB = fmaxf(mxB, fmaxf(sacc[nb][2], sacc[nb][3]));
        }
        mxA = fmaxf(mxA, __shfl_xor_sync(0xffffffffu, mxA, 1));
        mxA = fmaxf(mxA, __shfl_xor_sync(0xffffffffu, mxA, 2));
        mxB = fmaxf(mxB, __shfl_xor_sync(0xffffffffu, mxB, 1));
        mxB = fmaxf(mxB, __shfl_xor_sync(0xffffffffu, mxB, 2));
        float mnA = fmaxf(m0, mxA), mnB = fmaxf(m1, mxB);
        float cA = __expf(m0 - mnA), cB = __expf(m1 - mnB);
        m0 = mnA; m1 = mnB;
        float rsA = 0.f, rsB = 0.f;
#pragma unroll
        for (int nb = 0; nb < 8; nb++) {
            sacc[nb][0] = __expf(sacc[nb][0] - mnA);
            sacc[nb][1] = __expf(sacc[nb][1] - mnA);
            sacc[nb][2] = __expf(sacc[nb][2] - mnB);
            sacc[nb][3] = __expf(sacc[nb][3] - mnB);
            rsA += sacc[nb][0] + sacc[nb][1];
            rsB += sacc[nb][2] + sacc[nb][3];
        }
        rsA += __shfl_xor_sync(0xffffffffu, rsA, 1);
        rsA += __shfl_xor_sync(0xffffffffu, rsA, 2);
        rsB += __shfl_xor_sync(0xffffffffu, rsB, 1);
        rsB += __shfl_xor_sync(0xffffffffu, rsB, 2);
        l0 = l0 * cA + rsA;
        l1 = l1 * cB + rsB;
#pragma unroll
        for (int db = 0; db < 8; db++) {
            oacc[db][0] *= cA; oacc[db][1] *= cA;
            oacc[db][2] *= cB; oacc[db][3] *= cB;
        }

        // pack P fragments
        uint32_t a0[4], a1[4], a2[4], a3[4];
#pragma unroll
        for (int s2 = 0; s2 < 4; s2++) {
            a0[s2] = packh2(sacc[2 * s2][0],     sacc[2 * s2][1]);
            a1[s2] = packh2(sacc[2 * s2][2],     sacc[2 * s2][3]);
            a2[s2] = packh2(sacc[2 * s2 + 1][0], sacc[2 * s2 + 1][1]);
            a3[s2] = packh2(sacc[2 * s2 + 1][2], sacc[2 * s2 + 1][3]);
        }

        // O += P V
#pragma unroll
        for (int db = 0; db < 8; db++) {
            int rr = db * 8 + r_in;
#pragma unroll
            for (int kp = 0; kp < 2; kp++) {
                uint32_t u = (uint32_t)(kp * 4 + sub) ^ (uint32_t)(rr & 7);
                uint32_t vfr[4];
                ldmx4(vfr, vbase + (uint32_t)db * 1024 + lrow + u * 16);
                int s0 = 2 * kp, s1 = s0 + 1;
                mmaf16(oacc[db], a0[s0], a1[s0], a2[s0], a3[s0], vfr[0], vfr[1]);
                mmaf16(oacc[db], a0[s1], a1[s1], a2[s1], a3[s1], vfr[2], vfr[3]);
            }
        }
        st = snext;
    }

    float iA = 1.f / l0, iB = 1.f / l1;
#pragma unroll
    for (int db = 0; db < 8; db++) {
        int c = db * 8 + 2 * tg;
        *(uint32_t*)(O + baseQ + (size_t)(row0 + rA) * EMB + c) =
            packh2(oacc[db][0] * iA, oacc[db][1] * iA);
        *(uint32_t*)(O + baseQ + (size_t)(row0 + rB) * EMB + c) =
            packh2(oacc[db][2] * iB, oacc[db][3] * iB);
    }
}

// ======================= host orchestration =================================
extern "C" void kernel_launch(void* const* d_in, const int* in_sizes, int n_in,
                              void* d_out, int out_size) {
    const float* x     = (const float*)d_in[0];
    const float* Wq    = (const float*)d_in[1];
    const float* Wk    = (const float*)d_in[2];
    const float* Wv    = (const float*)d_in[3];
    const float* Wproj = (const float*)d_in[4];
    const float* bproj = (const float*)d_in[5];
    const float* W1    = (const float*)d_in[6];
    const float* b1    = (const float*)d_in[7];
    const float* W2    = (const float*)d_in[8];
    const float* b2    = (const float*)d_in[9];
    const float* g1    = (const float*)d_in[10];
    const float* be1   = (const float*)d_in[11];
    const float* g2    = (const float*)d_in[12];
    const float* be2   = (const float*)d_in[13];
    float* out = (float*)d_out;

    void *ph, *pq, *pk, *pv, *pvt, *pattn, *px1, *pffn;
    void *pwq, *pwk, *pwv, *pwp, *pw1, *pw2;
    cudaGetSymbolAddress(&ph,    g_h);
    cudaGetSymbolAddress(&pq,    g_q);
    cudaGetSymbolAddress(&pk,    g_k);
    cudaGetSymbolAddress(&pv,    g_v);
    cudaGetSymbolAddress(&pvt,   g_vt);
    cudaGetSymbolAddress(&pattn, g_attn);
    cudaGetSymbolAddress(&px1,   g_x1);
    cudaGetSymbolAddress(&pffn,  g_ffn);
    cudaGetSymbolAddress(&pwq,   g_wqt);
    cudaGetSymbolAddress(&pwk,   g_wkt);
    cudaGetSymbolAddress(&pwv,   g_wvt);
    cudaGetSymbolAddress(&pwp,   g_wpt);
    cudaGetSymbolAddress(&pw1,   g_w1t);
    cudaGetSymbolAddress(&pw2,   g_w2t);
    __half* f_h    = (__half*)ph;
    __half* f_q    = (__half*)pq;
    __half* f_k    = (__half*)pk;
    __half* f_v    = (__half*)pv;
    __half* f_vt   = (__half*)pvt;
    __half* f_attn = (__half*)pattn;
    float*  f_x1   = (float*)px1;
    __half* f_ffn  = (__half*)pffn;

    cudaFuncSetAttribute(gemm_mma, cudaFuncAttributeMaxDynamicSharedMemorySize,
                         G_SMEM);
    cudaFuncSetAttribute(flash_mma, cudaFuncAttributeMaxDynamicSharedMemorySize,
                         FL_SMEM);

    dim3 tb(32, 8);
    dim3 gP(EMB / 128, ROWS / 128);     // (8, 32)
    dim3 gF1(FFDIM / 128, ROWS / 128);  // (32, 32)

    ln_kernel<<<ROWS, 256>>>(x, g1, be1, f_h);
    transpose_w<<<dim3(EMB / 32, EMB / 32), tb>>>(Wq, (__half*)pwq, EMB, EMB, 1);
    transpose_w<<<dim3(EMB / 32, EMB / 32), tb>>>(Wk, (__half*)pwk, EMB, EMB, 1);
    transpose_w<<<dim3(EMB / 32, EMB / 32), tb>>>(Wv, (__half*)pwv, EMB, EMB, 1);
    transpose_w<<<dim3(EMB / 32, EMB / 32), tb>>>(Wproj, (__half*)pwp, EMB, EMB, 0);

    gemm_mma<<<gP, 256, G_SMEM>>>(f_h, (__half*)pwq, f_q, nullptr, nullptr, 0, EMB, EMB, 1);
    gemm_mma<<<gP, 256, G_SMEM>>>(f_h, (__half*)pwk, f_k, nullptr, nullptr, 0, EMB, EMB, 1);
    gemm_mma<<<gP, 256, G_SMEM>>>(f_h, (__half*)pwv, f_v, nullptr, nullptr, 0, EMB, EMB, 1);

    transpose_v<<<dim3(SEQ / 32, DHEAD / 32, 32), tb>>>(
        (const unsigned short*)pv, (unsigned short*)pvt);
    flash_mma<<<dim3(SEQ / 128, 32), 256, FL_SMEM>>>(f_q, f_k, f_vt, f_attn);

    gemm_mma<<<gP, 256, G_SMEM>>>(f_attn, (__half*)pwp, f_x1, bproj, x, 0, EMB, EMB, 0);
    ln_kernel<<<ROWS, 256>>>(f_x1, g2, be2, f_h);

    transpose_w<<<dim3(FFDIM / 32, EMB / 32), tb>>>(W1, (__half*)pw1, EMB, FFDIM, 0);
    transpose_w<<<dim3(EMB / 32, FFDIM / 32), tb>>>(W2, (__half*)pw2, FFDIM, EMB, 0);

    gemm_mma<<<gF1, 256, G_SMEM>>>(f_h, (__half*)pw1, f_ffn, b1, nullptr, 1, EMB, FFDIM, 1);
    gemm_mma<<<gP, 256, G_SMEM>>>(f_ffn, (__half*)pw2, out, b2, f_x1, 0, FFDIM, EMB, 0);
}

// round 15
// speedup vs baseline: 1.1546x; 1.0146x over previous
#include <cuda_runtime.h>
#include <cuda_fp16.h>
#include <cstdint>
#include <cstddef>

// Problem constants
#define BATCH 2
#define SEQ   2048
#define EMB   1024
#define HEADS 16
#define DHEAD 64
#define ROWS  (BATCH*SEQ)          // 4096
#define FFDIM (4*EMB)              // 4096
#define QKVN  (3*EMB)              // 3072

// ---------------- scratch (allocation-free: __device__ globals) ----------------
__device__ unsigned short g_h   [ROWS*EMB];
__device__ unsigned short g_qkv [ROWS*QKVN];      // fused [Q|K|V], row stride 3072
__device__ unsigned short g_vt  [32*DHEAD*SEQ];   // V transposed: [bh][d][s]
__device__ unsigned short g_attn[ROWS*EMB];
__device__ unsigned short g_ffn [ROWS*FFDIM];
__device__ float          g_x1  [ROWS*EMB];
// transposed weights, [N, K] K-major, fp16
__device__ unsigned short g_wqkvt[QKVN*EMB];      // rows: 0..1023 Wq, 1024.. Wk, 2048.. Wv
__device__ unsigned short g_wpt [EMB*EMB];
__device__ unsigned short g_w1t [EMB*FFDIM];
__device__ unsigned short g_w2t [FFDIM*EMB];

// ======================= PTX helpers =========================================
__device__ __forceinline__ uint32_t smem_u32(const void* p) {
    uint32_t a;
    asm("{ .reg .u64 t; cvta.to.shared.u64 t, %1; cvt.u32.u64 %0, t; }"
        : "=r"(a) : "l"(p));
    return a;
}
#define CP_ASYNC16(dst, src) \
    asm volatile("cp.async.cg.shared.global [%0], [%1], 16;" \
                 :: "r"(dst), "l"(src) : "memory")
#define CP_COMMIT() asm volatile("cp.async.commit_group;" ::: "memory")
#define CP_WAIT1()  asm volatile("cp.async.wait_group 1;"  ::: "memory")
__device__ __forceinline__ void ldmx4(uint32_t* r, uint32_t addr) {
    asm volatile("ldmatrix.sync.aligned.m8n8.x4.shared.b16 {%0,%1,%2,%3}, [%4];"
                 : "=r"(r[0]), "=r"(r[1]), "=r"(r[2]), "=r"(r[3]) : "r"(addr));
}
__device__ __forceinline__ uint32_t packh2(float lo, float hi) {
    __half2 h = __floats2half2_rn(lo, hi);
    return *reinterpret_cast<uint32_t*>(&h);
}
__device__ __forceinline__ void mmaf16(float* c,
                                       uint32_t a0, uint32_t a1,
                                       uint32_t a2, uint32_t a3,
                                       uint32_t b0, uint32_t b1) {
    asm volatile(
        "mma.sync.aligned.m16n8k16.row.col.f32.f16.f16.f32 "
        "{%0,%1,%2,%3}, {%4,%5,%6,%7}, {%8,%9}, {%0,%1,%2,%3};"
        : "+f"(c[0]), "+f"(c[1]), "+f"(c[2]), "+f"(c[3])
        : "r"(a0), "r"(a1), "r"(a2), "r"(a3), "r"(b0), "r"(b1));
}

// ======================= tensor-core fp16 GEMM (R8 measured version) =========
// C[M,N] = A[M,K]*Bt[N,K]^T, fp16 in / fp32 accum.
// BM=BN=128, BK=64 halves (128B/row, 8 x 16B units), XOR-8 swizzle col^(row&7).
// 3-stage cp.async ring (32KB/stage -> 2 CTAs/SM); 256 thr, warp tile 64x32.
#define G_STAGE 32768              // A 16KB + B 16KB
#define G_SMEM  (3 * G_STAGE)      // 98304

__global__ void __launch_bounds__(256)
gemm_mma(const __half* __restrict__ A, const __half* __restrict__ Bt,
         void* __restrict__ Cv,
         const float* __restrict__ bias,
         const float* __restrict__ residual,
         int doRelu, int K, int N, int halfOut) {
    extern __shared__ __align__(128) char smem[];
    uint32_t sbase = smem_u32(smem);
    int t = threadIdx.x;
    int lane = t & 31, wid = t >> 5;
    int g = lane >> 2, tg = lane & 3;
    int warp_m = wid & 1, warp_n = wid >> 1;
    int m0 = blockIdx.y * 128, n0 = blockIdx.x * 128;

    int ld_row = t >> 1, ld_c0 = (t & 1) * 4;
    const __half* Arow = A  + (size_t)(m0 + ld_row) * K;
    const __half* Brow = Bt + (size_t)(n0 + ld_row) * K;
    int ld_swz = ld_row & 7;
    uint32_t ld_off = (uint32_t)ld_row * 128;

    int sub = lane >> 3, r_in = lane & 7;
    uint32_t a_row[4], a_swz[4];
#pragma unroll
    for (int mf = 0; mf < 4; mf++) {
        int r = warp_m * 64 + mf * 16 + (sub & 1) * 8 + r_in;
        a_row[mf] = (uint32_t)r * 128;
        a_swz[mf] = (uint32_t)(r & 7);
    }
    int a_du = sub >> 1;
    uint32_t b_row[4], b_swz[4];
#pragma unroll
    for (int nf = 0; nf < 4; nf++) {
        int r = warp_n * 32 + nf * 8 + r_in;
        b_row[nf] = (uint32_t)r * 128;
        b_swz[nf] = (uint32_t)(r & 7);
    }

    float acc[4][4][4];
#pragma unroll
    for (int i = 0; i < 4; i++)
#pragma unroll
        for (int j = 0; j < 4; j++)
#pragma unroll
            for (int r = 0; r < 4; r++) acc[i][j][r] = 0.f;

#define G_ISSUE(s, k0)                                                        \
    do {                                                                      \
        uint32_t ab_ = sbase + (s) * G_STAGE + ld_off;                        \
        uint32_t bb_ = ab_ + 16384;                                           \
        _Pragma("unroll")                                                     \
        for (int j = 0; j < 4; j++) {                                         \
            int c_ = ld_c0 + j;                                               \
            uint32_t cp_ = (uint32_t)(c_ ^ ld_swz) * 16;                      \
            CP_ASYNC16(ab_ + cp_, Arow + (k0) + c_ * 8);                      \
            CP_ASYNC16(bb_ + cp_, Brow + (k0) + c_ * 8);                      \
        }                                                                     \
    } while (0)

    int NKt = K >> 6;
    G_ISSUE(0, 0);  CP_COMMIT();
    G_ISSUE(1, 64); CP_COMMIT();

    int s = 0;
    for (int it = 0; it < NKt; it++) {
        CP_WAIT1();
        __syncthreads();
        int snext = (s == 2) ? 0 : s + 1;
        int sfill = (snext == 2) ? 0 : snext + 1;
        if (it + 2 < NKt) G_ISSUE(sfill, (it + 2) << 6);
        CP_COMMIT();

        uint32_t abase = sbase + s * G_STAGE;
        uint32_t bbase = abase + 16384;
#pragma unroll
        for (int kp = 0; kp < 2; kp++) {
            uint32_t bfr[4][4];
#pragma unroll
            for (int nf = 0; nf < 4; nf++) {
                uint32_t u = (uint32_t)(kp * 4 + sub) ^ b_swz[nf];
                ldmx4(bfr[nf], bbase + b_row[nf] + u * 16);
            }
#pragma unroll
            for (int kss = 0; kss < 2; kss++) {
                int ks = kp * 2 + kss;
                uint32_t afr[4][4];
#pragma unroll
                for (int mf = 0; mf < 4; mf++) {
                    uint32_t u = (uint32_t)(2 * ks + a_du) ^ a_swz[mf];
                    ldmx4(afr[mf], abase + a_row[mf] + u * 16);
                }
#pragma unroll
                for (int mf = 0; mf < 4; mf++)
#pragma unroll
                    for (int nf = 0; nf < 4; nf++)
                        mmaf16(acc[mf][nf],
                               afr[mf][0], afr[mf][1], afr[mf][2], afr[mf][3],
                               bfr[nf][kss * 2], bfr[nf][kss * 2 + 1]);
            }
        }
        s = snext;
    }

    // epilogue
#pragma unroll
    for (int mf = 0; mf < 4; mf++) {
#pragma unroll
        for (int nf = 0; nf < 4; nf++) {
            int row = m0 + warp_m * 64 + mf * 16 + g;
            int col = n0 + warp_n * 32 + nf * 8 + 2 * tg;
            float b0 = 0.f, b1 = 0.f;
            if (bias) { b0 = bias[col]; b1 = bias[col + 1]; }
#pragma unroll
            for (int rr = 0; rr < 2; rr++) {
                int r = row + rr * 8;
                float v0 = acc[mf][nf][rr * 2 + 0] + b0;
                float v1 = acc[mf][nf][rr * 2 + 1] + b1;
                if (doRelu) { v0 = fmaxf(v0, 0.f); v1 = fmaxf(v1, 0.f); }
                if (residual) {
                    float2 rv = *(const float2*)(residual + (size_t)r * N + col);
                    v0 += rv.x; v1 += rv.y;
                }
                if (halfOut) {
                    *(uint32_t*)((__half*)Cv + (size_t)r * N + col) = packh2(v0, v1);
                } else {
                    *(float2*)((float*)Cv + (size_t)r * N + col) = make_float2(v0, v1);
                }
            }
        }
    }
}

// ======================= fused attention-weight transpose ====================
// z=0..2: Wq/Wk/Wv (head layout) -> g_wqkvt rows z*1024.. ; z=3: Wproj -> g_wpt
__global__ void transpose_w4(const float* __restrict__ Wq,
                             const float* __restrict__ Wk,
                             const float* __restrict__ Wv,
                             const float* __restrict__ Wp,
                             __half* __restrict__ outQKV,
                             __half* __restrict__ outP) {
    __shared__ float tile[32][33];
    int z = blockIdx.z;
    const float* in = (z == 0) ? Wq : (z == 1) ? Wk : (z == 2) ? Wv : Wp;
    __half* out = (z < 3) ? (outQKV + (size_t)z * EMB * EMB) : outP;
    int headMode = (z < 3) ? 1 : 0;
    int K = EMB;
    int k0 = blockIdx.y * 32, n0 = blockIdx.x * 32;
    int tx = threadIdx.x, ty = threadIdx.y;
    for (int i = ty; i < 32; i += 8) {
        int k = k0 + i, n = n0 + tx;
        float v = headMode
            ? in[(size_t)(n >> 6) * K * 64 + (size_t)k * 64 + (n & 63)]
            : in[(size_t)k * EMB + n];
        tile[i][tx] = v;
    }
    __syncthreads();
    for (int i = ty; i < 32; i += 8) {
        out[(size_t)(n0 + i) * K + k0 + tx] = __float2half(tile[tx][i]);
    }
}

// ======================= generic weight transpose (W1/W2) ====================
__global__ void transpose_w(const float* __restrict__ in, __half* __restrict__ out,
                            int K, int N) {
    __shared__ float tile[32][33];
    int k0 = blockIdx.y * 32, n0 = blockIdx.x * 32;
    int tx = threadIdx.x, ty = threadIdx.y;
    for (int i = ty; i < 32; i += 8)
        tile[i][tx] = in[(size_t)(k0 + i) * N + n0 + tx];
    __syncthreads();
    for (int i = ty; i < 32; i += 8)
        out[(size_t)(n0 + i) * K + k0 + tx] = __float2half(tile[tx][i]);
}

// ======================= V transpose: g_qkv V cols -> [bh][d][s] =============
__global__ void transpose_v(const unsigned short* __restrict__ qkv,
                            unsigned short* __restrict__ vt) {
    __shared__ unsigned short tile[32][33];
    int bh = blockIdx.z;
    int s0 = blockIdx.x * 32, d0 = blockIdx.y * 32;
    int b = bh >> 4, h = bh & 15;
    int tx = threadIdx.x, ty = threadIdx.y;
    for (int i = ty; i < 32; i += 8)
        tile[i][tx] = qkv[(size_t)(b * SEQ + s0 + i) * QKVN
                          + 2 * EMB + h * 64 + d0 + tx];
    __syncthreads();
    for (int i = ty; i < 32; i += 8)
        vt[((size_t)bh * 64 + d0 + i) * SEQ + s0 + tx] = tile[tx][i];
}

// ======================= LayerNorm (fp32 in -> fp16 out) =====================
__global__ void ln_kernel(const float* __restrict__ x,
                          const float* __restrict__ g,
                          const float* __restrict__ b,
                          __half* __restrict__ out) {
    int row = blockIdx.x;
    const float* xr = x + (size_t)row * EMB;
    float v[4];
    float s = 0.f, ss = 0.f;
#pragma unroll
    for (int i = 0; i < 4; i++) {
        v[i] = xr[threadIdx.x + i * 256];
        s += v[i]; ss += v[i] * v[i];
    }
#pragma unroll
    for (int m = 16; m; m >>= 1) {
        s  += __shfl_xor_sync(0xffffffffu, s,  m);
        ss += __shfl_xor_sync(0xffffffffu, ss, m);
    }
    __shared__ float red[2][8];
    int warp = threadIdx.x >> 5, lane = threadIdx.x & 31;
    if (lane == 0) { red[0][warp] = s; red[1][warp] = ss; }
    __syncthreads();
    float S = 0.f, SS = 0.f;
#pragma unroll
    for (int w = 0; w < 8; w++) { S += red[0][w]; SS += red[1][w]; }
    float mean = S * (1.f / EMB);
    float var  = SS * (1.f / EMB) - mean * mean;
    float inv  = rsqrtf(var + 1e-5f);
    __half* orow = out + (size_t)row * EMB;
#pragma unroll
    for (int i = 0; i < 4; i++) {
        int e = threadIdx.x + i * 256;
        orow[e] = __float2half((v[i] - mean) * inv * g[e] + b[e]);
    }
}

// ======================= Flash attention (R8 measured version) ===============
// Br=128 (8 warps x 16 rows), Bc=64, d=64; P in registers.
// Q/K read from fused QKV tensor (row stride 3072); O written stride 1024.
#define FQSLAB 520
#define FKSLAB 264
#define FQSUB  2080
#define FKSUB  1056
#define LDQK   QKVN

__global__ void __launch_bounds__(256)
flash_mma(const __half* __restrict__ Q, const __half* __restrict__ Kg,
          const __half* __restrict__ Vt, __half* __restrict__ O) {
    __shared__ uint32_t Qs[2 * FQSUB];
    __shared__ uint32_t Ks[2 * FKSUB];
    __shared__ uint32_t Vs[2 * FKSUB];
    int t = threadIdx.x, lane = t & 31, w = t >> 5;
    int g = lane >> 2, tg = lane & 3;
    int bh = blockIdx.y;
    int row0 = blockIdx.x * 128;
    size_t baseQK = (size_t)(bh >> 4) * SEQ * LDQK + (size_t)(bh & 15) * DHEAD;
    size_t baseO  = (size_t)(bh >> 4) * SEQ * EMB  + (size_t)(bh & 15) * DHEAD;
    size_t baseV  = (size_t)bh * DHEAD * SEQ;
    const __half2 qscale = __float2half2_rn(0.125f);

    for (int i = t; i < 1024; i += 256) {
        int r = i >> 3, q = i & 7;
        uint4 p = *(const uint4*)(Q + baseQK + (size_t)(row0 + r) * LDQK + q * 8);
        uint32_t un[4] = {p.x, p.y, p.z, p.w};
#pragma unroll
        for (int jj = 0; jj < 4; jj++) {
            __half2 hv = *reinterpret_cast<__half2*>(&un[jj]);
            hv = __hmul2(hv, qscale);
            int u = q * 4 + jj;
            int s_ = u >> 4, uu = u & 15;
            Qs[s_ * FQSUB + (uu & 3) * FQSLAB + r * 4 + (uu >> 2)]
                = *reinterpret_cast<uint32_t*>(&hv);
        }
    }
    __syncthreads();

    int rA = w * 16 + g, rB = rA + 8;
    uint4 qfA[2], qfB[2];
#pragma unroll
    for (int sub = 0; sub < 2; sub++) {
        qfA[sub] = *(const uint4*)&Qs[sub * FQSUB + tg * FQSLAB + rA * 4];
        qfB[sub] = *(const uint4*)&Qs[sub * FQSUB + tg * FQSLAB + rB * 4];
    }

    float m0 = -1e30f, m1 = -1e30f, l0 = 0.f, l1 = 0.f;
    float oacc[8][4];
#pragma unroll
    for (int i = 0; i < 8; i++)
#pragma unroll
        for (int j = 0; j < 4; j++) oacc[i][j] = 0.f;

    for (int kt = 0; kt < SEQ; kt += 64) {
        __syncthreads();
#pragma unroll
        for (int ii = 0; ii < 2; ii++) {
            int i = t + ii * 256;
            int r = i >> 3, q = i & 7;
            uint4 pk = *(const uint4*)(Kg + baseQK + (size_t)(kt + r) * LDQK + q * 8);
            uint4 pv = *(const uint4*)(Vt + baseV + (size_t)r * SEQ + kt + q * 8);
            uint32_t ku[4] = {pk.x, pk.y, pk.z, pk.w};
            uint32_t vu[4] = {pv.x, pv.y, pv.z, pv.w};
#pragma unroll
            for (int jj = 0; jj < 4; jj++) {
                int u = q * 4 + jj;
                int s_ = u >> 4, uu = u & 15;
                int off = s_ * FKSUB + (uu & 3) * FKSLAB + r * 4 + (uu >> 2);
                Ks[off] = ku[jj];
                Vs[off] = vu[jj];
            }
        }
        __syncthreads();

        float sacc[8][4];
#pragma unroll
        for (int i = 0; i < 8; i++)
#pragma unroll
            for (int j = 0; j < 4; j++) sacc[i][j] = 0.f;
#pragma unroll
        for (int sub = 0; sub < 2; sub++) {
            uint4 qa = qfA[sub], qb = qfB[sub];
#pragma unroll
            for (int nb = 0; nb < 8; nb++) {
                uint4 kf = *(const uint4*)&Ks[sub * FKSUB + tg * FKSLAB
                                              + (nb * 8 + g) * 4];
                mmaf16(sacc[nb], qa.x, qb.x, qa.y, qb.y, kf.x, kf.y);
                mmaf16(sacc[nb], qa.z, qb.z, qa.w, qb.w, kf.z, kf.w);
            }
        }

        float mxA = -1e30f, mxB = -1e30f;
#pragma unroll
        for (int nb = 0; nb < 8; nb++) {
            mxA = fmaxf(mxA, fmaxf(sacc[nb][0], sacc[nb][1]));
            mxB = fmaxf(mxB, fmaxf(sacc[nb][2], sacc[nb][3]));
        }
        mxA = fmaxf(mxA, __shfl_xor_sync(0xffffffffu, mxA, 1));
        mxA = fmaxf(mxA, __shfl_xor_sync(0xffffffffu, mxA, 2));
        mxB = fmaxf(mxB, __shfl_xor_sync(0xffffffffu, mxB, 1));
        mxB = fmaxf(mxB, __shfl_xor_sync(0xffffffffu, mxB, 2));
        float mnA = fmaxf(m0, mxA), mnB = fmaxf(m1, mxB);
        float cA = __expf(m0 - mnA), cB = __expf(m1 - mnB);
        m0 = mnA; m1 = mnB;
        float rsA = 0.f, rsB = 0.f;
#pragma unroll
        for (int nb = 0; nb < 8; nb++) {
            sacc[nb][0] = __expf(sacc[nb][0] - mnA);
            sacc[nb][1] = __expf(sacc[nb][1] - mnA);
            sacc[nb][2] = __expf(sacc[nb][2] - mnB);
            sacc[nb][3] = __expf(sacc[nb][3] - mnB);
            rsA += sacc[nb][0] + sacc[nb][1];
            rsB += sacc[nb][2] + sacc[nb][3];
        }
        rsA += __shfl_xor_sync(0xffffffffu, rsA, 1);
        rsA += __shfl_xor_sync(0xffffffffu, rsA, 2);
        rsB += __shfl_xor_sync(0xffffffffu, rsB, 1);
        rsB += __shfl_xor_sync(0xffffffffu, rsB, 2);
        l0 = l0 * cA + rsA;
        l1 = l1 * cB + rsB;
#pragma unroll
        for (int db = 0; db < 8; db++) {
            oacc[db][0] *= cA; oacc[db][1] *= cA;
            oacc[db][2] *= cB; oacc[db][3] *= cB;
        }

        uint32_t a0[4], a1[4], a2[4], a3[4];
#pragma unroll
        for (int s = 0; s < 4; s++) {
            a0[s] = packh2(sacc[2 * s][0],     sacc[2 * s][1]);
            a1[s] = packh2(sacc[2 * s][2],     sacc[2 * s][3]);
            a2[s] = packh2(sacc[2 * s + 1][0], sacc[2 * s + 1][1]);
            a3[s] = packh2(sacc[2 * s + 1][2], sacc[2 * s + 1][3]);
        }

#pragma unroll
        for (int db = 0; db < 8; db++)
#pragma unroll
            for (int sub = 0; sub < 2; sub++) {
                uint4 vf = *(const uint4*)&Vs[sub * FKSUB + tg * FKSLAB
                                              + (db * 8 + g) * 4];
                int s0 = 2 * sub, s1 = s0 + 1;
                mmaf16(oacc[db], a0[s0], a1[s0], a2[s0], a3[s0], vf.x, vf.y);
                mmaf16(oacc[db], a0[s1], a1[s1], a2[s1], a3[s1], vf.z, vf.w);
            }
    }

    float iA = 1.f / l0, iB = 1.f / l1;
#pragma unroll
    for (int db = 0; db < 8; db++) {
        int c = db * 8 + 2 * tg;
        *(uint32_t*)(O + baseO + (size_t)(row0 + rA) * EMB + c) =
            packh2(oacc[db][0] * iA, oacc[db][1] * iA);
        *(uint32_t*)(O + baseO + (size_t)(row0 + rB) * EMB + c) =
            packh2(oacc[db][2] * iB, oacc[db][3] * iB);
    }
}

// ======================= host orchestration =================================
extern "C" void kernel_launch(void* const* d_in, const int* in_sizes, int n_in,
                              void* d_out, int out_size) {
    const float* x     = (const float*)d_in[0];
    const float* Wq    = (const float*)d_in[1];
    const float* Wk    = (const float*)d_in[2];
    const float* Wv    = (const float*)d_in[3];
    const float* Wproj = (const float*)d_in[4];
    const float* bproj = (const float*)d_in[5];
    const float* W1    = (const float*)d_in[6];
    const float* b1    = (const float*)d_in[7];
    const float* W2    = (const float*)d_in[8];
    const float* b2    = (const float*)d_in[9];
    const float* g1    = (const float*)d_in[10];
    const float* be1   = (const float*)d_in[11];
    const float* g2    = (const float*)d_in[12];
    const float* be2   = (const float*)d_in[13];
    float* out = (float*)d_out;

    void *ph, *pqkv, *pvt, *pattn, *px1, *pffn;
    void *pwqkv, *pwp, *pw1, *pw2;
    cudaGetSymbolAddress(&ph,    g_h);
    cudaGetSymbolAddress(&pqkv,  g_qkv);
    cudaGetSymbolAddress(&pvt,   g_vt);
    cudaGetSymbolAddress(&pattn, g_attn);
    cudaGetSymbolAddress(&px1,   g_x1);
    cudaGetSymbolAddress(&pffn,  g_ffn);
    cudaGetSymbolAddress(&pwqkv, g_wqkvt);
    cudaGetSymbolAddress(&pwp,   g_wpt);
    cudaGetSymbolAddress(&pw1,   g_w1t);
    cudaGetSymbolAddress(&pw2,   g_w2t);
    __half* f_h    = (__half*)ph;
    __half* f_qkv  = (__half*)pqkv;
    __half* f_vt   = (__half*)pvt;
    __half* f_attn = (__half*)pattn;
    float*  f_x1   = (float*)px1;
    __half* f_ffn  = (__half*)pffn;

    cudaFuncSetAttribute(gemm_mma, cudaFuncAttributeMaxDynamicSharedMemorySize,
                         G_SMEM);

    dim3 tb(32, 8);
    dim3 gQKV(QKVN / 128, ROWS / 128);  // (24, 32)
    dim3 gP(EMB / 128, ROWS / 128);     // (8, 32)
    dim3 gF1(FFDIM / 128, ROWS / 128);  // (32, 32)

    ln_kernel<<<ROWS, 256>>>(x, g1, be1, f_h);
    transpose_w4<<<dim3(EMB / 32, EMB / 32, 4), tb>>>(
        Wq, Wk, Wv, Wproj, (__half*)pwqkv, (__half*)pwp);

    // fused QKV projection: M=4096, N=3072, K=1024
    gemm_mma<<<gQKV, 256, G_SMEM>>>(f_h, (__half*)pwqkv, f_qkv,
                                    nullptr, nullptr, 0, EMB, QKVN, 1);

    transpose_v<<<dim3(SEQ / 32, DHEAD / 32, 32), tb>>>(
        (const unsigned short*)pqkv, (unsigned short*)pvt);
    flash_mma<<<dim3(SEQ / 128, 32), 256>>>(f_qkv, f_qkv + EMB, f_vt, f_attn);

    gemm_mma<<<gP, 256, G_SMEM>>>(f_attn, (__half*)pwp, f_x1, bproj, x,
                                  0, EMB, EMB, 0);
    ln_kernel<<<ROWS, 256>>>(f_x1, g2, be2, f_h);

    transpose_w<<<dim3(FFDIM / 32, EMB / 32), tb>>>(W1, (__half*)pw1, EMB, FFDIM);
    transpose_w<<<dim3(EMB / 32, FFDIM / 32), tb>>>(W2, (__half*)pw2, FFDIM, EMB);

    gemm_mma<<<gF1, 256, G_SMEM>>>(f_h, (__half*)pw1, f_ffn, b1, nullptr,
                                   1, EMB, FFDIM, 1);
    gemm_mma<<<gP, 256, G_SMEM>>>(f_ffn, (__half*)pw2, out, b2, f_x1,
                                  0, FFDIM, EMB, 0);
}

// round 17
// speedup vs baseline: 1.1849x; 1.0263x over previous
#include <cuda_runtime.h>
#include <cuda_fp16.h>
#include <cstdint>
#include <cstddef>

// Problem constants
#define BATCH 2
#define SEQ   2048
#define EMB   1024
#define HEADS 16
#define DHEAD 64
#define ROWS  (BATCH*SEQ)          // 4096
#define FFDIM (4*EMB)              // 4096
#define QKVN  (3*EMB)              // 3072

// ---------------- scratch (allocation-free: __device__ globals) ----------------
__device__ unsigned short g_h   [ROWS*EMB];
__device__ unsigned short g_qkv [ROWS*QKVN];      // fused [Q|K|V], row stride 3072
__device__ unsigned short g_vt  [32*DHEAD*SEQ];   // V transposed: [bh][d][s]
__device__ unsigned short g_attn[ROWS*EMB];
__device__ unsigned short g_ffn [ROWS*FFDIM];
__device__ float          g_x1  [ROWS*EMB];
// transposed weights, [N, K] K-major, fp16
__device__ unsigned short g_wqkvt[QKVN*EMB];
__device__ unsigned short g_wpt [EMB*EMB];
__device__ unsigned short g_w1t [EMB*FFDIM];
__device__ unsigned short g_w2t [FFDIM*EMB];

// ======================= PTX helpers =========================================
__device__ __forceinline__ uint32_t smem_u32(const void* p) {
    uint32_t a;
    asm("{ .reg .u64 t; cvta.to.shared.u64 t, %1; cvt.u32.u64 %0, t; }"
        : "=r"(a) : "l"(p));
    return a;
}
#define CP_ASYNC16(dst, src) \
    asm volatile("cp.async.cg.shared.global [%0], [%1], 16;" \
                 :: "r"(dst), "l"(src) : "memory")
#define CP_COMMIT() asm volatile("cp.async.commit_group;" ::: "memory")
#define CP_WAIT1()  asm volatile("cp.async.wait_group 1;"  ::: "memory")
__device__ __forceinline__ void ldmx4(uint32_t* r, uint32_t addr) {
    asm volatile("ldmatrix.sync.aligned.m8n8.x4.shared.b16 {%0,%1,%2,%3}, [%4];"
                 : "=r"(r[0]), "=r"(r[1]), "=r"(r[2]), "=r"(r[3]) : "r"(addr));
}
__device__ __forceinline__ uint32_t packh2(float lo, float hi) {
    __half2 h = __floats2half2_rn(lo, hi);
    return *reinterpret_cast<uint32_t*>(&h);
}
__device__ __forceinline__ void mmaf16(float* c,
                                       uint32_t a0, uint32_t a1,
                                       uint32_t a2, uint32_t a3,
                                       uint32_t b0, uint32_t b1) {
    asm volatile(
        "mma.sync.aligned.m16n8k16.row.col.f32.f16.f16.f32 "
        "{%0,%1,%2,%3}, {%4,%5,%6,%7}, {%8,%9}, {%0,%1,%2,%3};"
        : "+f"(c[0]), "+f"(c[1]), "+f"(c[2]), "+f"(c[3])
        : "r"(a0), "r"(a1), "r"(a2), "r"(a3), "r"(b0), "r"(b1));
}

// ======================= tensor-core fp16 GEMM (R8 measured version) =========
#define G_STAGE 32768              // A 16KB + B 16KB
#define G_SMEM  (3 * G_STAGE)      // 98304

__global__ void __launch_bounds__(256)
gemm_mma(const __half* __restrict__ A, const __half* __restrict__ Bt,
         void* __restrict__ Cv,
         const float* __restrict__ bias,
         const float* __restrict__ residual,
         int doRelu, int K, int N, int halfOut) {
    extern __shared__ __align__(128) char smem[];
    uint32_t sbase = smem_u32(smem);
    int t = threadIdx.x;
    int lane = t & 31, wid = t >> 5;
    int g = lane >> 2, tg = lane & 3;
    int warp_m = wid & 1, warp_n = wid >> 1;
    int m0 = blockIdx.y * 128, n0 = blockIdx.x * 128;

    int ld_row = t >> 1, ld_c0 = (t & 1) * 4;
    const __half* Arow = A  + (size_t)(m0 + ld_row) * K;
    const __half* Brow = Bt + (size_t)(n0 + ld_row) * K;
    int ld_swz = ld_row & 7;
    uint32_t ld_off = (uint32_t)ld_row * 128;

    int sub = lane >> 3, r_in = lane & 7;
    uint32_t a_row[4], a_swz[4];
#pragma unroll
    for (int mf = 0; mf < 4; mf++) {
        int r = warp_m * 64 + mf * 16 + (sub & 1) * 8 + r_in;
        a_row[mf] = (uint32_t)r * 128;
        a_swz[mf] = (uint32_t)(r & 7);
    }
    int a_du = sub >> 1;
    uint32_t b_row[4], b_swz[4];
#pragma unroll
    for (int nf = 0; nf < 4; nf++) {
        int r = warp_n * 32 + nf * 8 + r_in;
        b_row[nf] = (uint32_t)r * 128;
        b_swz[nf] = (uint32_t)(r & 7);
    }

    float acc[4][4][4];
#pragma unroll
    for (int i = 0; i < 4; i++)
#pragma unroll
        for (int j = 0; j < 4; j++)
#pragma unroll
            for (int r = 0; r < 4; r++) acc[i][j][r] = 0.f;

#define G_ISSUE(s, k0)                                                        \
    do {                                                                      \
        uint32_t ab_ = sbase + (s) * G_STAGE + ld_off;                        \
        uint32_t bb_ = ab_ + 16384;                                           \
        _Pragma("unroll")                                                     \
        for (int j = 0; j < 4; j++) {                                         \
            int c_ = ld_c0 + j;                                               \
            uint32_t cp_ = (uint32_t)(c_ ^ ld_swz) * 16;                      \
            CP_ASYNC16(ab_ + cp_, Arow + (k0) + c_ * 8);                      \
            CP_ASYNC16(bb_ + cp_, Brow + (k0) + c_ * 8);                      \
        }                                                                     \
    } while (0)

    int NKt = K >> 6;
    G_ISSUE(0, 0);  CP_COMMIT();
    G_ISSUE(1, 64); CP_COMMIT();

    int s = 0;
    for (int it = 0; it < NKt; it++) {
        CP_WAIT1();
        __syncthreads();
        int snext = (s == 2) ? 0 : s + 1;
        int sfill = (snext == 2) ? 0 : snext + 1;
        if (it + 2 < NKt) G_ISSUE(sfill, (it + 2) << 6);
        CP_COMMIT();

        uint32_t abase = sbase + s * G_STAGE;
        uint32_t bbase = abase + 16384;
#pragma unroll
        for (int kp = 0; kp < 2; kp++) {
            uint32_t bfr[4][4];
#pragma unroll
            for (int nf = 0; nf < 4; nf++) {
                uint32_t u = (uint32_t)(kp * 4 + sub) ^ b_swz[nf];
                ldmx4(bfr[nf], bbase + b_row[nf] + u * 16);
            }
#pragma unroll
            for (int kss = 0; kss < 2; kss++) {
                int ks = kp * 2 + kss;
                uint32_t afr[4][4];
#pragma unroll
                for (int mf = 0; mf < 4; mf++) {
                    uint32_t u = (uint32_t)(2 * ks + a_du) ^ a_swz[mf];
                    ldmx4(afr[mf], abase + a_row[mf] + u * 16);
                }
#pragma unroll
                for (int mf = 0; mf < 4; mf++)
#pragma unroll
                    for (int nf = 0; nf < 4; nf++)
                        mmaf16(acc[mf][nf],
                               afr[mf][0], afr[mf][1], afr[mf][2], afr[mf][3],
                               bfr[nf][kss * 2], bfr[nf][kss * 2 + 1]);
            }
        }
        s = snext;
    }

    // epilogue
#pragma unroll
    for (int mf = 0; mf < 4; mf++) {
#pragma unroll
        for (int nf = 0; nf < 4; nf++) {
            int row = m0 + warp_m * 64 + mf * 16 + g;
            int col = n0 + warp_n * 32 + nf * 8 + 2 * tg;
            float b0 = 0.f, b1 = 0.f;
            if (bias) { b0 = bias[col]; b1 = bias[col + 1]; }
#pragma unroll
            for (int rr = 0; rr < 2; rr++) {
                int r = row + rr * 8;
                float v0 = acc[mf][nf][rr * 2 + 0] + b0;
                float v1 = acc[mf][nf][rr * 2 + 1] + b1;
                if (doRelu) { v0 = fmaxf(v0, 0.f); v1 = fmaxf(v1, 0.f); }
                if (residual) {
                    float2 rv = *(const float2*)(residual + (size_t)r * N + col);
                    v0 += rv.x; v1 += rv.y;
                }
                if (halfOut) {
                    *(uint32_t*)((__half*)Cv + (size_t)r * N + col) = packh2(v0, v1);
                } else {
                    *(float2*)((float*)Cv + (size_t)r * N + col) = make_float2(v0, v1);
                }
            }
        }
    }
}

// ======================= fused attention-weight transpose ====================
__global__ void transpose_w4(const float* __restrict__ Wq,
                             const float* __restrict__ Wk,
                             const float* __restrict__ Wv,
                             const float* __restrict__ Wp,
                             __half* __restrict__ outQKV,
                             __half* __restrict__ outP) {
    __shared__ float tile[32][33];
    int z = blockIdx.z;
    const float* in = (z == 0) ? Wq : (z == 1) ? Wk : (z == 2) ? Wv : Wp;
    __half* out = (z < 3) ? (outQKV + (size_t)z * EMB * EMB) : outP;
    int headMode = (z < 3) ? 1 : 0;
    int K = EMB;
    int k0 = blockIdx.y * 32, n0 = blockIdx.x * 32;
    int tx = threadIdx.x, ty = threadIdx.y;
    for (int i = ty; i < 32; i += 8) {
        int k = k0 + i, n = n0 + tx;
        float v = headMode
            ? in[(size_t)(n >> 6) * K * 64 + (size_t)k * 64 + (n & 63)]
            : in[(size_t)k * EMB + n];
        tile[i][tx] = v;
    }
    __syncthreads();
    for (int i = ty; i < 32; i += 8) {
        out[(size_t)(n0 + i) * K + k0 + tx] = __float2half(tile[tx][i]);
    }
}

// ======================= generic weight transpose (W1/W2) ====================
__global__ void transpose_w(const float* __restrict__ in, __half* __restrict__ out,
                            int K, int N) {
    __shared__ float tile[32][33];
    int k0 = blockIdx.y * 32, n0 = blockIdx.x * 32;
    int tx = threadIdx.x, ty = threadIdx.y;
    for (int i = ty; i < 32; i += 8)
        tile[i][tx] = in[(size_t)(k0 + i) * N + n0 + tx];
    __syncthreads();
    for (int i = ty; i < 32; i += 8)
        out[(size_t)(n0 + i) * K + k0 + tx] = __float2half(tile[tx][i]);
}

// ======================= V transpose: g_qkv V cols -> [bh][d][s] =============
__global__ void transpose_v(const unsigned short* __restrict__ qkv,
                            unsigned short* __restrict__ vt) {
    __shared__ unsigned short tile[32][33];
    int bh = blockIdx.z;
    int s0 = blockIdx.x * 32, d0 = blockIdx.y * 32;
    int b = bh >> 4, h = bh & 15;
    int tx = threadIdx.x, ty = threadIdx.y;
    for (int i = ty; i < 32; i += 8)
        tile[i][tx] = qkv[(size_t)(b * SEQ + s0 + i) * QKVN
                          + 2 * EMB + h * 64 + d0 + tx];
    __syncthreads();
    for (int i = ty; i < 32; i += 8)
        vt[((size_t)bh * 64 + d0 + i) * SEQ + s0 + tx] = tile[tx][i];
}

// ======================= LayerNorm (fp32 in -> fp16 out) =====================
__global__ void ln_kernel(const float* __restrict__ x,
                          const float* __restrict__ g,
                          const float* __restrict__ b,
                          __half* __restrict__ out) {
    int row = blockIdx.x;
    const float* xr = x + (size_t)row * EMB;
    float v[4];
    float s = 0.f, ss = 0.f;
#pragma unroll
    for (int i = 0; i < 4; i++) {
        v[i] = xr[threadIdx.x + i * 256];
        s += v[i]; ss += v[i] * v[i];
    }
#pragma unroll
    for (int m = 16; m; m >>= 1) {
        s  += __shfl_xor_sync(0xffffffffu, s,  m);
        ss += __shfl_xor_sync(0xffffffffu, ss, m);
    }
    __shared__ float red[2][8];
    int warp = threadIdx.x >> 5, lane = threadIdx.x & 31;
    if (lane == 0) { red[0][warp] = s; red[1][warp] = ss; }
    __syncthreads();
    float S = 0.f, SS = 0.f;
#pragma unroll
    for (int w = 0; w < 8; w++) { S += red[0][w]; SS += red[1][w]; }
    float mean = S * (1.f / EMB);
    float var  = SS * (1.f / EMB) - mean * mean;
    float inv  = rsqrtf(var + 1e-5f);
    __half* orow = out + (size_t)row * EMB;
#pragma unroll
    for (int i = 0; i < 4; i++) {
        int e = threadIdx.x + i * 256;
        orow[e] = __float2half((v[i] - mean) * inv * g[e] + b[e]);
    }
}

// ======================= Flash attention, K/V double-buffered ================
// Br=128 (8 warps x 16 rows), Bc=64, d=64; P in registers.
// LDG for tile i+1 issued before compute of tile i; STS after; 1 sync/tile.
// Dynamic smem (50432 B > 48KB static cap): Qs | Ks(2 buf) | Vs(2 buf)
#define FQSLAB 520
#define FKSLAB 264
#define FQSUB  2080
#define FKSUB  1056
#define FKBUF  (2*FKSUB)                     // 2112 u32 per buffer
#define FL_QW  (2*FQSUB)                     // 4160 u32
#define FL_KW  (2*FKBUF)                     // 4224 u32
#define FL_SMEM ((FL_QW + 2*FL_KW) * 4)      // 50432 bytes
#define LDQK   QKVN

__global__ void __launch_bounds__(256, 2)
flash_mma(const __half* __restrict__ Q, const __half* __restrict__ Kg,
          const __half* __restrict__ Vt, __half* __restrict__ O) {
    extern __shared__ __align__(128) uint32_t fsm[];
    uint32_t* Qs = fsm;
    uint32_t* Ks = fsm + FL_QW;
    uint32_t* Vs = fsm + FL_QW + FL_KW;
    int t = threadIdx.x, lane = t & 31, w = t >> 5;
    int g = lane >> 2, tg = lane & 3;
    int bh = blockIdx.y;
    int row0 = blockIdx.x * 128;
    size_t baseQK = (size_t)(bh >> 4) * SEQ * LDQK + (size_t)(bh & 15) * DHEAD;
    size_t baseO  = (size_t)(bh >> 4) * SEQ * EMB  + (size_t)(bh & 15) * DHEAD;
    size_t baseV  = (size_t)bh * DHEAD * SEQ;
    const __half2 qscale = __float2half2_rn(0.125f);

    uint4 pk[2], pv[2];
#define F_LDG(kt0)                                                            \
    do {                                                                      \
        _Pragma("unroll")                                                     \
        for (int ii = 0; ii < 2; ii++) {                                      \
            int i_ = t + ii * 256;                                            \
            int r_ = i_ >> 3, q_ = i_ & 7;                                    \
            pk[ii] = *(const uint4*)(Kg + baseQK                              \
                       + (size_t)((kt0) + r_) * LDQK + q_ * 8);               \
            pv[ii] = *(const uint4*)(Vt + baseV                               \
                       + (size_t)r_ * SEQ + (kt0) + q_ * 8);                  \
        }                                                                     \
    } while (0)
#define F_STS(kb)                                                             \
    do {                                                                      \
        _Pragma("unroll")                                                     \
        for (int ii = 0; ii < 2; ii++) {                                      \
            int i_ = t + ii * 256;                                            \
            int r_ = i_ >> 3, q_ = i_ & 7;                                    \
            uint32_t ku_[4] = {pk[ii].x, pk[ii].y, pk[ii].z, pk[ii].w};       \
            uint32_t vu_[4] = {pv[ii].x, pv[ii].y, pv[ii].z, pv[ii].w};       \
            _Pragma("unroll")                                                 \
            for (int jj = 0; jj < 4; jj++) {                                  \
                int u_ = q_ * 4 + jj;                                         \
                int s_ = u_ >> 4, uu_ = u_ & 15;                              \
                int off_ = (kb) + s_ * FKSUB + (uu_ & 3) * FKSLAB             \
                           + r_ * 4 + (uu_ >> 2);                             \
                Ks[off_] = ku_[jj];                                           \
                Vs[off_] = vu_[jj];                                           \
            }                                                                 \
        }                                                                     \
    } while (0)

    // load Q tile (scale by 2^-3)
    for (int i = t; i < 1024; i += 256) {
        int r = i >> 3, q = i & 7;
        uint4 p = *(const uint4*)(Q + baseQK + (size_t)(row0 + r) * LDQK + q * 8);
        uint32_t un[4] = {p.x, p.y, p.z, p.w};
#pragma unroll
        for (int jj = 0; jj < 4; jj++) {
            __half2 hv = *reinterpret_cast<__half2*>(&un[jj]);
            hv = __hmul2(hv, qscale);
            int u = q * 4 + jj;
            int s_ = u >> 4, uu = u & 15;
            Qs[s_ * FQSUB + (uu & 3) * FQSLAB + r * 4 + (uu >> 2)]
                = *reinterpret_cast<uint32_t*>(&hv);
        }
    }
    // preload tile 0 into buffer 0
    F_LDG(0);
    F_STS(0);
    __syncthreads();

    int rA = w * 16 + g, rB = rA + 8;
    uint4 qfA[2], qfB[2];
#pragma unroll
    for (int sub = 0; sub < 2; sub++) {
        qfA[sub] = *(const uint4*)&Qs[sub * FQSUB + tg * FQSLAB + rA * 4];
        qfB[sub] = *(const uint4*)&Qs[sub * FQSUB + tg * FQSLAB + rB * 4];
    }

    float m0 = -1e30f, m1 = -1e30f, l0 = 0.f, l1 = 0.f;
    float oacc[8][4];
#pragma unroll
    for (int i = 0; i < 8; i++)
#pragma unroll
        for (int j = 0; j < 4; j++) oacc[i][j] = 0.f;

    for (int it = 0; it < 32; it++) {
        int kb = (it & 1) * FKBUF;
        if (it + 1 < 32) F_LDG((it + 1) * 64);   // overlaps compute below

        // S = Q K^T
        float sacc[8][4];
#pragma unroll
        for (int i = 0; i < 8; i++)
#pragma unroll
            for (int j = 0; j < 4; j++) sacc[i][j] = 0.f;
#pragma unroll
        for (int sub = 0; sub < 2; sub++) {
            uint4 qa = qfA[sub], qb = qfB[sub];
#pragma unroll
            for (int nb = 0; nb < 8; nb++) {
                uint4 kf = *(const uint4*)&Ks[kb + sub * FKSUB + tg * FKSLAB
                                              + (nb * 8 + g) * 4];
                mmaf16(sacc[nb], qa.x, qb.x, qa.y, qb.y, kf.x, kf.y);
                mmaf16(sacc[nb], qa.z, qb.z, qa.w, qb.w, kf.z, kf.w);
            }
        }

        // online softmax
        float mxA = -1e30f, mxB = -1e30f;
#pragma unroll
        for (int nb = 0; nb < 8; nb++) {
            mxA = fmaxf(mxA, fmaxf(sacc[nb][0], sacc[nb][1]));
            mxB = fmaxf(mxB, fmaxf(sacc[nb][2], sacc[nb][3]));
        }
        mxA = fmaxf(mxA, __shfl_xor_sync(0xffffffffu, mxA, 1));
        mxA = fmaxf(mxA, __shfl_xor_sync(0xffffffffu, mxA, 2));
        mxB = fmaxf(mxB, __shfl_xor_sync(0xffffffffu, mxB, 1));
        mxB = fmaxf(mxB, __shfl_xor_sync(0xffffffffu, mxB, 2));
        float mnA = fmaxf(m0, mxA), mnB = fmaxf(m1, mxB);
        float cA = __expf(m0 - mnA), cB = __expf(m1 - mnB);
        m0 = mnA; m1 = mnB;
        float rsA = 0.f, rsB = 0.f;
#pragma unroll
        for (int nb = 0; nb < 8; nb++) {
            sacc[nb][0] = __expf(sacc[nb][0] - mnA);
            sacc[nb][1] = __expf(sacc[nb][1] - mnA);
            sacc[nb][2] = __expf(sacc[nb][2] - mnB);
            sacc[nb][3] = __expf(sacc[nb][3] - mnB);
            rsA += sacc[nb][0] + sacc[nb][1];
            rsB += sacc[nb][2] + sacc[nb][3];
        }
        rsA += __shfl_xor_sync(0xffffffffu, rsA, 1);
        rsA += __shfl_xor_sync(0xffffffffu, rsA, 2);
        rsB += __shfl_xor_sync(0xffffffffu, rsB, 1);
        rsB += __shfl_xor_sync(0xffffffffu, rsB, 2);
        l0 = l0 * cA + rsA;
        l1 = l1 * cB + rsB;
#pragma unroll
        for (int db = 0; db < 8; db++) {
            oacc[db][0] *= cA; oacc[db][1] *= cA;
            oacc[db][2] *= cB; oacc[db][3] *= cB;
        }

        uint32_t a0[4], a1[4], a2[4], a3[4];
#pragma unroll
        for (int s = 0; s < 4; s++) {
            a0[s] = packh2(sacc[2 * s][0],     sacc[2 * s][1]);
            a1[s] = packh2(sacc[2 * s][2],     sacc[2 * s][3]);
            a2[s] = packh2(sacc[2 * s + 1][0], sacc[2 * s + 1][1]);
            a3[s] = packh2(sacc[2 * s + 1][2], sacc[2 * s + 1][3]);
        }

        // O += P V
#pragma unroll
        for (int db = 0; db < 8; db++)
#pragma unroll
            for (int sub = 0; sub < 2; sub++) {
                uint4 vf = *(const uint4*)&Vs[kb + sub * FKSUB + tg * FKSLAB
                                              + (db * 8 + g) * 4];
                int s0 = 2 * sub, s1 = s0 + 1;
                mmaf16(oacc[db], a0[s0], a1[s0], a2[s0], a3[s0], vf.x, vf.y);
                mmaf16(oacc[db], a0[s1], a1[s1], a2[s1], a3[s1], vf.z, vf.w);
            }

        if (it + 1 < 32) F_STS(((it + 1) & 1) * FKBUF);
        __syncthreads();
    }

    float iA = 1.f / l0, iB = 1.f / l1;
#pragma unroll
    for (int db = 0; db < 8; db++) {
        int c = db * 8 + 2 * tg;
        *(uint32_t*)(O + baseO + (size_t)(row0 + rA) * EMB + c) =
            packh2(oacc[db][0] * iA, oacc[db][1] * iA);
        *(uint32_t*)(O + baseO + (size_t)(row0 + rB) * EMB + c) =
            packh2(oacc[db][2] * iB, oacc[db][3] * iB);
    }
}

// ======================= host orchestration =================================
extern "C" void kernel_launch(void* const* d_in, const int* in_sizes, int n_in,
                              void* d_out, int out_size) {
    const float* x     = (const float*)d_in[0];
    const float* Wq    = (const float*)d_in[1];
    const float* Wk    = (const float*)d_in[2];
    const float* Wv    = (const float*)d_in[3];
    const float* Wproj = (const float*)d_in[4];
    const float* bproj = (const float*)d_in[5];
    const float* W1    = (const float*)d_in[6];
    const float* b1    = (const float*)d_in[7];
    const float* W2    = (const float*)d_in[8];
    const float* b2    = (const float*)d_in[9];
    const float* g1    = (const float*)d_in[10];
    const float* be1   = (const float*)d_in[11];
    const float* g2    = (const float*)d_in[12];
    const float* be2   = (const float*)d_in[13];
    float* out = (float*)d_out;

    void *ph, *pqkv, *pvt, *pattn, *px1, *pffn;
    void *pwqkv, *pwp, *pw1, *pw2;
    cudaGetSymbolAddress(&ph,    g_h);
    cudaGetSymbolAddress(&pqkv,  g_qkv);
    cudaGetSymbolAddress(&pvt,   g_vt);
    cudaGetSymbolAddress(&pattn, g_attn);
    cudaGetSymbolAddress(&px1,   g_x1);
    cudaGetSymbolAddress(&pffn,  g_ffn);
    cudaGetSymbolAddress(&pwqkv, g_wqkvt);
    cudaGetSymbolAddress(&pwp,   g_wpt);
    cudaGetSymbolAddress(&pw1,   g_w1t);
    cudaGetSymbolAddress(&pw2,   g_w2t);
    __half* f_h    = (__half*)ph;
    __half* f_qkv  = (__half*)pqkv;
    __half* f_vt   = (__half*)pvt;
    __half* f_attn = (__half*)pattn;
    float*  f_x1   = (float*)px1;
    __half* f_ffn  = (__half*)pffn;

    cudaFuncSetAttribute(gemm_mma, cudaFuncAttributeMaxDynamicSharedMemorySize,
                         G_SMEM);
    cudaFuncSetAttribute(flash_mma, cudaFuncAttributeMaxDynamicSharedMemorySize,
                         FL_SMEM);

    dim3 tb(32, 8);
    dim3 gQKV(QKVN / 128, ROWS / 128);  // (24, 32)
    dim3 gP(EMB / 128, ROWS / 128);     // (8, 32)
    dim3 gF1(FFDIM / 128, ROWS / 128);  // (32, 32)

    // launch order: position 4 = fused QKV gemm (ncu capture slot)
    ln_kernel<<<ROWS, 256>>>(x, g1, be1, f_h);                              // 1
    transpose_w4<<<dim3(EMB / 32, EMB / 32, 4), tb>>>(
        Wq, Wk, Wv, Wproj, (__half*)pwqkv, (__half*)pwp);                   // 2
    transpose_w<<<dim3(FFDIM / 32, EMB / 32), tb>>>(W1, (__half*)pw1,
                                                    EMB, FFDIM);            // 3
    gemm_mma<<<gQKV, 256, G_SMEM>>>(f_h, (__half*)pwqkv, f_qkv,
                                    nullptr, nullptr, 0, EMB, QKVN, 1);     // 4 <- ncu
    transpose_v<<<dim3(SEQ / 32, DHEAD / 32, 32), tb>>>(
        (const unsigned short*)pqkv, (unsigned short*)pvt);                 // 5
    flash_mma<<<dim3(SEQ / 128, 32), 256, FL_SMEM>>>(f_qkv, f_qkv + EMB,
                                                     f_vt, f_attn);         // 6
    gemm_mma<<<gP, 256, G_SMEM>>>(f_attn, (__half*)pwp, f_x1, bproj, x,
                                  0, EMB, EMB, 0);                          // 7
    ln_kernel<<<ROWS, 256>>>(f_x1, g2, be2, f_h);                           // 8
    transpose_w<<<dim3(EMB / 32, FFDIM / 32), tb>>>(W2, (__half*)pw2,
                                                    FFDIM, EMB);            // 9
    gemm_mma<<<gF1, 256, G_SMEM>>>(f_h, (__half*)pw1, f_ffn, b1, nullptr,
                                   1, EMB, FFDIM, 1);                       // 10
    gemm_mma<<<gP, 256, G_SMEM>>>(f_ffn, (__half*)pw2, out, b2, f_x1,
                                  0, FFDIM, EMB, 0);                        // 11
}